// round 9
// baseline (speedup 1.0000x reference)
#include <cuda_runtime.h>
#include <cuda_bf16.h>
#include <cstdint>
#include <math.h>

#define Bv 2
#define Sv 2048
#define Ev 1024
#define Hv 16
#define Dv 64
#define Mtot (Bv * Sv)          // 4096

enum { MODE_ROPEQ = 0, MODE_ROPEK = 1, MODE_BHSD = 2, MODE_PLAIN = 3 };

// ---------------- scratch (__device__ globals; no allocs allowed) ----------
__device__ __nv_bfloat16 g_Qhi[Bv * Hv * Sv * Dv], g_Qlo[Bv * Hv * Sv * Dv];
__device__ __nv_bfloat16 g_Khi[Bv * Hv * Sv * Dv], g_Klo[Bv * Hv * Sv * Dv];
__device__ __nv_bfloat16 g_Vhi[Bv * Hv * Sv * Dv], g_Vlo[Bv * Hv * Sv * Dv];
__device__ __nv_bfloat16 g_xhi[Mtot * Ev], g_xlo[Mtot * Ev];
__device__ __nv_bfloat16 g_ohi[Mtot * Ev], g_olo[Mtot * Ev];
__device__ __nv_bfloat16 g_wqhi[Ev * Ev], g_wqlo[Ev * Ev];
__device__ __nv_bfloat16 g_wkhi[Ev * Ev], g_wklo[Ev * Ev];
__device__ __nv_bfloat16 g_wvhi[Ev * Ev], g_wvlo[Ev * Ev];
__device__ __nv_bfloat16 g_wohi[Ev * Ev], g_wolo[Ev * Ev];

// ---------------- helpers --------------------------------------------------
__device__ __forceinline__ uint32_t smem_to_u32(const void* p) {
    uint32_t a;
    asm("{ .reg .u64 t; cvta.to.shared.u64 t, %1; cvt.u32.u64 %0, t; }"
        : "=r"(a) : "l"(p));
    return a;
}

__device__ __forceinline__ void ldmatrix_x4(uint32_t* r, uint32_t addr) {
    asm volatile("ldmatrix.sync.aligned.m8n8.x4.shared.b16 {%0,%1,%2,%3}, [%4];"
                 : "=r"(r[0]), "=r"(r[1]), "=r"(r[2]), "=r"(r[3]) : "r"(addr));
}
__device__ __forceinline__ void ldmatrix_x4t(uint32_t* r, uint32_t addr) {
    asm volatile("ldmatrix.sync.aligned.m8n8.x4.trans.shared.b16 {%0,%1,%2,%3}, [%4];"
                 : "=r"(r[0]), "=r"(r[1]), "=r"(r[2]), "=r"(r[3]) : "r"(addr));
}

__device__ __forceinline__ void mma16816(float* c, const uint32_t* a,
                                         const uint32_t* b) {
    asm volatile(
        "mma.sync.aligned.m16n8k16.row.col.f32.bf16.bf16.f32 "
        "{%0,%1,%2,%3}, {%4,%5,%6,%7}, {%8,%9}, {%0,%1,%2,%3};"
        : "+f"(c[0]), "+f"(c[1]), "+f"(c[2]), "+f"(c[3])
        : "r"(a[0]), "r"(a[1]), "r"(a[2]), "r"(a[3]), "r"(b[0]), "r"(b[1]));
}

#define CP_ASYNC16(smem, gptr) \
    asm volatile("cp.async.cg.shared.global [%0], [%1], 16;" \
                 :: "r"(smem), "l"(gptr))
#define CP_COMMIT() asm volatile("cp.async.commit_group;" ::: "memory")
#define CP_WAIT2()  asm volatile("cp.async.wait_group 2;" ::: "memory")
#define CP_WAIT1()  asm volatile("cp.async.wait_group 1;" ::: "memory")

// sincos accurate under --use_fast_math (Cody-Waite 2*pi reduction)
__device__ __forceinline__ void sincos_red(float ang, float* s, float* c) {
    float kf = rintf(ang * 0.15915494309189535f);
    float r = fmaf(kf, -6.2831854820251465f, ang);
    r = fmaf(kf, 1.7484555e-7f, r);
    __sincosf(r, s, c);
}

// split two fp32 into packed bf16x2 (hi) + packed bf16x2 (residual lo)
__device__ __forceinline__ void split_pack(float p0, float p1,
                                           uint32_t& hi, uint32_t& lo) {
    __nv_bfloat16 h0 = __float2bfloat16(p0), h1 = __float2bfloat16(p1);
    float r0 = p0 - __bfloat162float(h0), r1 = p1 - __bfloat162float(h1);
    __nv_bfloat162 hp; hp.x = h0; hp.y = h1;
    __nv_bfloat162 lp; lp.x = __float2bfloat16(r0); lp.y = __float2bfloat16(r1);
    hi = *(uint32_t*)&hp; lo = *(uint32_t*)&lp;
}

// ---------------------------------------------------------------------------
// fp32 -> (hi, lo) bf16 splits
// ---------------------------------------------------------------------------
__global__ __launch_bounds__(256)
void split_bf16_kernel(const float* __restrict__ src,
                       __nv_bfloat16* __restrict__ hi,
                       __nv_bfloat16* __restrict__ lo)
{
    int i = (blockIdx.x * 256 + threadIdx.x) * 4;
    float4 v = *(const float4*)(src + i);
    uint32_t hA, lA, hB, lB;
    split_pack(v.x, v.y, hA, lA);
    split_pack(v.z, v.w, hB, lB);
    *(uint32_t*)&hi[i]     = hA;
    *(uint32_t*)&hi[i + 2] = hB;
    *(uint32_t*)&lo[i]     = lA;
    *(uint32_t*)&lo[i + 2] = lB;
}

__global__ __launch_bounds__(256)
void split4_kernel(const float* __restrict__ w0, const float* __restrict__ w1,
                   const float* __restrict__ w2, const float* __restrict__ w3,
                   __nv_bfloat16* __restrict__ h0, __nv_bfloat16* __restrict__ l0,
                   __nv_bfloat16* __restrict__ h1, __nv_bfloat16* __restrict__ l1,
                   __nv_bfloat16* __restrict__ h2, __nv_bfloat16* __restrict__ l2,
                   __nv_bfloat16* __restrict__ h3, __nv_bfloat16* __restrict__ l3)
{
    int y = blockIdx.y;
    const float* src = (y == 0) ? w0 : (y == 1) ? w1 : (y == 2) ? w2 : w3;
    __nv_bfloat16* hi = (y == 0) ? h0 : (y == 1) ? h1 : (y == 2) ? h2 : h3;
    __nv_bfloat16* lo = (y == 0) ? l0 : (y == 1) ? l1 : (y == 2) ? l2 : l3;
    int i = (blockIdx.x * 256 + threadIdx.x) * 4;
    float4 v = *(const float4*)(src + i);
    uint32_t hA, lA, hB, lB;
    split_pack(v.x, v.y, hA, lA);
    split_pack(v.z, v.w, hB, lB);
    *(uint32_t*)&hi[i]     = hA;
    *(uint32_t*)&hi[i + 2] = hB;
    *(uint32_t*)&lo[i]     = lA;
    *(uint32_t*)&lo[i + 2] = lB;
}

// ---------------------------------------------------------------------------
// bf16x3 GEMM core via mma.sync: C[m,n] = sum_k A[m,k]*W[n,k] + bias[n].
// CTA: 128(M) x 256(N), 8 warps (2x4), warp tile 64x64. K-chunks of 32.
// Term-ordered inner loop (ah*bh, al*bh, ah*bl) to minimize live registers.
// ---------------------------------------------------------------------------
#define GBK 32
#define GNCHUNK (Ev / GBK)               // 32
#define ATB (128 * 80)
#define WTB (256 * 80)
#define STAGEB (2 * ATB + 2 * WTB)       // 61440
#define NSTG 3
#define GEMM_SMEM (NSTG * STAGEB + 256)

__device__ __forceinline__
void gemm_core(const __nv_bfloat16* __restrict__ Ahi,
               const __nv_bfloat16* __restrict__ Alo,
               const __nv_bfloat16* __restrict__ Whi,
               const __nv_bfloat16* __restrict__ Wlo,
               const float* __restrict__ bias,
               float* __restrict__ dstf,
               __nv_bfloat16* __restrict__ dsthi,
               __nv_bfloat16* __restrict__ dstlo, int mode)
{
    extern __shared__ char dsm[];
    uint32_t base = (smem_to_u32(dsm) + 127) & ~127u;

    const int tid = threadIdx.x;
    const int wid = tid >> 5, lid = tid & 31;
    const int wm = wid >> 2, wn = wid & 3;
    const int m0 = blockIdx.y * 128, n0 = blockIdx.x * 256;

    const __nv_bfloat16* Aho = Ahi + (size_t)m0 * Ev;
    const __nv_bfloat16* Alo2 = Alo + (size_t)m0 * Ev;
    const __nv_bfloat16* Who = Whi + (size_t)n0 * Ev;
    const __nv_bfloat16* Wlo2 = Wlo + (size_t)n0 * Ev;

    auto load_chunk = [&](int c, int s) {
        const int k0 = c * GBK;
        uint32_t sb = base + s * STAGEB;
        #pragma unroll
        for (int it = 0; it < 12; it++) {
            int e = it * 256 + tid;
            int c16 = e & 3;
            int grow = e >> 2;
            uint32_t so;
            const __nv_bfloat16* g;
            if (grow < 256) {
                int sub = grow >> 7, row = grow & 127;
                so = sb + sub * ATB + row * 80 + c16 * 16;
                g = (sub ? Alo2 : Aho) + (size_t)row * Ev + k0 + c16 * 8;
            } else {
                int gw = grow - 256;
                int sub = gw >> 8, row = gw & 255;
                so = sb + 2 * ATB + sub * WTB + row * 80 + c16 * 16;
                g = (sub ? Wlo2 : Who) + (size_t)row * Ev + k0 + c16 * 8;
            }
            CP_ASYNC16(so, g);
        }
    };

    float acc[4][8][4] = {};

    const uint32_t aoff = (lid & 15) * 80 + (lid >> 4) * 16;
    const uint32_t boff = ((lid >> 4) * 8 + (lid & 7)) * 80 + ((lid >> 3) & 1) * 16;

    #pragma unroll
    for (int s = 0; s < NSTG; s++) { load_chunk(s, s); CP_COMMIT(); }

    for (int c = 0; c < GNCHUNK; c++) {
        int s = c % NSTG;
        CP_WAIT2();
        __syncthreads();

        uint32_t sb  = base + s * STAGEB;
        uint32_t aHI = sb + (wm * 64) * 80;
        uint32_t aLO = aHI + ATB;
        uint32_t bHI = sb + 2 * ATB + (wn * 64) * 80;
        uint32_t bLO = bHI + WTB;

        #pragma unroll
        for (int ks = 0; ks < 2; ks++) {
            uint32_t kb = ks * 32;
            // -- B-hi frags for all 8 nt --
            uint32_t bh[8][2];
            #pragma unroll
            for (int pr = 0; pr < 4; pr++) {
                uint32_t t4[4];
                ldmatrix_x4(t4, bHI + pr * (16 * 80) + kb + boff);
                bh[2 * pr][0] = t4[0]; bh[2 * pr][1] = t4[1];
                bh[2 * pr + 1][0] = t4[2]; bh[2 * pr + 1][1] = t4[3];
            }
            // -- A-hi, term 1: ah*bh --
            uint32_t ah[4][4];
            #pragma unroll
            for (int mt = 0; mt < 4; mt++)
                ldmatrix_x4(ah[mt], aHI + mt * (16 * 80) + kb + aoff);
            #pragma unroll
            for (int mt = 0; mt < 4; mt++)
                #pragma unroll
                for (int nt = 0; nt < 8; nt++)
                    mma16816(acc[mt][nt], ah[mt], bh[nt]);
            // -- A-lo, term 2: al*bh --
            {
                uint32_t al[4][4];
                #pragma unroll
                for (int mt = 0; mt < 4; mt++)
                    ldmatrix_x4(al[mt], aLO + mt * (16 * 80) + kb + aoff);
                #pragma unroll
                for (int mt = 0; mt < 4; mt++)
                    #pragma unroll
                    for (int nt = 0; nt < 8; nt++)
                        mma16816(acc[mt][nt], al[mt], bh[nt]);
            }
            // -- B-lo, term 3: ah*bl --
            {
                uint32_t bl[8][2];
                #pragma unroll
                for (int pr = 0; pr < 4; pr++) {
                    uint32_t t4[4];
                    ldmatrix_x4(t4, bLO + pr * (16 * 80) + kb + boff);
                    bl[2 * pr][0] = t4[0]; bl[2 * pr][1] = t4[1];
                    bl[2 * pr + 1][0] = t4[2]; bl[2 * pr + 1][1] = t4[3];
                }
                #pragma unroll
                for (int mt = 0; mt < 4; mt++)
                    #pragma unroll
                    for (int nt = 0; nt < 8; nt++)
                        mma16816(acc[mt][nt], ah[mt], bl[nt]);
            }
        }
        __syncthreads();
        if (c + NSTG < GNCHUNK) load_chunk(c + NSTG, s);
        CP_COMMIT();
    }

    // ------------------- epilogue -------------------
    const int g4 = lid >> 2, t2 = lid & 3;
    const int h = (n0 + wn * 64) >> 6;
    float fe = 0.f, fo = 0.f;
    #pragma unroll
    for (int nt = 0; nt < 8; nt++) {
        int n = n0 + wn * 64 + nt * 8 + t2 * 2;
        float bi0 = bias[n], bi1 = bias[n + 1];
        int d = n & 63;
        if (mode == MODE_ROPEQ || mode == MODE_ROPEK) {
            fe = powf(10000.0f, -(float)(2 * (d & 31)) / 64.0f);
            fo = powf(10000.0f, -(float)(2 * ((d + 1) & 31)) / 64.0f);
        }
        #pragma unroll
        for (int mt = 0; mt < 4; mt++) {
            #pragma unroll
            for (int hf = 0; hf < 2; hf++) {
                int m = m0 + wm * 64 + mt * 16 + g4 + hf * 8;
                float v0 = acc[mt][nt][hf * 2 + 0] + bi0;
                float v1 = acc[mt][nt][hf * 2 + 1] + bi1;
                if (mode == MODE_PLAIN) {
                    float2 o = {v0, v1};
                    *(float2*)&dstf[(size_t)m * Ev + n] = o;
                } else {
                    int b = m >> 11, srow = m & 2047;
                    if (mode != MODE_BHSD) {
                        float pos = (float)srow;
                        float se, ce, so, co;
                        sincos_red(pos * fe, &se, &ce);
                        sincos_red(pos * fo, &so, &co);
                        float r0 = v0 * ce - v1 * se;
                        float r1 = v1 * co + v0 * so;
                        v0 = r0; v1 = r1;
                        if (mode == MODE_ROPEQ) { v0 *= 0.125f; v1 *= 0.125f; }
                    }
                    uint32_t hw, lw;
                    split_pack(v0, v1, hw, lw);
                    size_t off = (((size_t)(b * Hv + h) * Sv + srow) << 6) + d;
                    *(uint32_t*)&dsthi[off] = hw;
                    *(uint32_t*)&dstlo[off] = lw;
                }
            }
        }
    }
}

__global__ __launch_bounds__(256, 1)
void gemm_qkv_kernel(const __nv_bfloat16* __restrict__ xhi,
                     const __nv_bfloat16* __restrict__ xlo,
                     const __nv_bfloat16* __restrict__ wqhi, const __nv_bfloat16* __restrict__ wqlo,
                     const __nv_bfloat16* __restrict__ wkhi, const __nv_bfloat16* __restrict__ wklo,
                     const __nv_bfloat16* __restrict__ wvhi, const __nv_bfloat16* __restrict__ wvlo,
                     const float* __restrict__ bq, const float* __restrict__ bk,
                     const float* __restrict__ bv,
                     __nv_bfloat16* __restrict__ qhi, __nv_bfloat16* __restrict__ qlo,
                     __nv_bfloat16* __restrict__ khi, __nv_bfloat16* __restrict__ klo,
                     __nv_bfloat16* __restrict__ vhi, __nv_bfloat16* __restrict__ vlo)
{
    int z = blockIdx.z;
    const __nv_bfloat16* whi = (z == 0) ? wqhi : (z == 1) ? wkhi : wvhi;
    const __nv_bfloat16* wlo = (z == 0) ? wqlo : (z == 1) ? wklo : wvlo;
    const float* bias = (z == 0) ? bq : (z == 1) ? bk : bv;
    __nv_bfloat16* dhi = (z == 0) ? qhi : (z == 1) ? khi : vhi;
    __nv_bfloat16* dlo = (z == 0) ? qlo : (z == 1) ? klo : vlo;
    int mode = (z == 0) ? MODE_ROPEQ : (z == 1) ? MODE_ROPEK : MODE_BHSD;
    gemm_core(xhi, xlo, whi, wlo, bias, nullptr, dhi, dlo, mode);
}

__global__ __launch_bounds__(256, 1)
void gemm_final_kernel(const __nv_bfloat16* __restrict__ ohi,
                       const __nv_bfloat16* __restrict__ olo,
                       const __nv_bfloat16* __restrict__ wohi,
                       const __nv_bfloat16* __restrict__ wolo,
                       const float* __restrict__ bo, float* __restrict__ out)
{
    gemm_core(ohi, olo, wohi, wolo, bo, out, nullptr, nullptr, MODE_PLAIN);
}

// ---------------------------------------------------------------------------
// Flash attention via mma.sync, bf16x3. CTA = 64 queries of one (b,h),
// 128 threads (4 warps x 16 rows) -> 92KB smem, 2 CTAs/SM: softmax of one
// CTA overlaps MMAs of the other. K-tiles of 64, double-buffered cp.async.
// ---------------------------------------------------------------------------
#define PITCHB 144
#define NQ 64
#define QSMB (NQ * PITCHB)           // 9216
#define KVTILE (64 * PITCHB)         // 9216
#define KVSTG (4 * KVTILE)           // 36864
#define ATTN_SMEM (2 * QSMB + 2 * KVSTG)   // 92160

__global__ __launch_bounds__(128, 2)
void attn_mma_kernel(const __nv_bfloat16* __restrict__ Qhi,
                     const __nv_bfloat16* __restrict__ Qlo,
                     const __nv_bfloat16* __restrict__ Khi,
                     const __nv_bfloat16* __restrict__ Klo,
                     const __nv_bfloat16* __restrict__ Vhi,
                     const __nv_bfloat16* __restrict__ Vlo,
                     __nv_bfloat16* __restrict__ Ohi,
                     __nv_bfloat16* __restrict__ Olo)
{
    extern __shared__ char dsm[];
    uint32_t base = smem_to_u32(dsm);
    const int tid = threadIdx.x, wid = tid >> 5, lid = tid & 31;
    const int qt = (int)gridDim.x - 1 - (int)blockIdx.x;  // longest first
    const int bh = blockIdx.y;
    const int nkt = qt + 1;
    const size_t bhb = (size_t)bh * Sv * 64;

    const uint32_t qhib = base, qlob = base + QSMB;
    const uint32_t stg = base + 2 * QSMB;

    auto load_kv = [&](int kt, int s) {
        uint32_t sb = stg + s * KVSTG;
        const __nv_bfloat16* srcs[4] = {
            Khi + bhb + (size_t)kt * 64 * 64, Klo + bhb + (size_t)kt * 64 * 64,
            Vhi + bhb + (size_t)kt * 64 * 64, Vlo + bhb + (size_t)kt * 64 * 64 };
        #pragma unroll
        for (int it = 0; it < 16; it++) {
            int e = it * 128 + tid;
            int tl = e >> 9, r = (e >> 3) & 63, ch = e & 7;
            CP_ASYNC16(sb + tl * KVTILE + r * PITCHB + ch * 16,
                       srcs[tl] + r * 64 + ch * 8);
        }
    };

    {
        const __nv_bfloat16* gh = Qhi + bhb + (size_t)qt * NQ * 64;
        const __nv_bfloat16* gl = Qlo + bhb + (size_t)qt * NQ * 64;
        #pragma unroll
        for (int it = 0; it < 4; it++) {
            int e = it * 128 + tid;
            int r = e >> 3, ch = e & 7;
            CP_ASYNC16(qhib + r * PITCHB + ch * 16, gh + r * 64 + ch * 8);
            CP_ASYNC16(qlob + r * PITCHB + ch * 16, gl + r * 64 + ch * 8);
        }
        load_kv(0, 0);
        CP_COMMIT();
        if (nkt > 1) load_kv(1, 1);
        CP_COMMIT();
    }
    CP_WAIT1();
    __syncthreads();

    uint32_t qfh[4][4], qfl[4][4];
    {
        uint32_t qfo = (wid * 16 + (lid & 15)) * PITCHB + (lid >> 4) * 16;
        #pragma unroll
        for (int kc = 0; kc < 4; kc++) {
            ldmatrix_x4(qfh[kc], qhib + qfo + kc * 32);
            ldmatrix_x4(qfl[kc], qlob + qfo + kc * 32);
        }
    }

    float m0 = -1e30f, m1 = -1e30f, l0 = 0.f, l1 = 0.f;
    float accO[8][4] = {};

    const uint32_t kfo = ((lid >> 4) * 8 + (lid & 7)) * PITCHB + ((lid >> 3) & 1) * 16;
    const uint32_t vfo = (lid & 15) * PITCHB + (lid >> 4) * 16;
    const int g4 = lid >> 2, t2 = lid & 3;

    for (int kt = 0; kt < nkt; kt++) {
        uint32_t sb = stg + (kt & 1) * KVSTG;

        float S[8][4] = {};
        #pragma unroll
        for (int kc = 0; kc < 4; kc++) {
            #pragma unroll
            for (int n0t = 0; n0t < 4; n0t++) {
                uint32_t ka = sb + (n0t * 16) * PITCHB + kc * 32 + kfo;
                uint32_t kh[4], kl[4];
                ldmatrix_x4(kh, ka);
                ldmatrix_x4(kl, ka + KVTILE);
                mma16816(S[2 * n0t], qfh[kc], kh);
                mma16816(S[2 * n0t], qfh[kc], kl);
                mma16816(S[2 * n0t], qfl[kc], kh);
                mma16816(S[2 * n0t + 1], qfh[kc], kh + 2);
                mma16816(S[2 * n0t + 1], qfh[kc], kl + 2);
                mma16816(S[2 * n0t + 1], qfl[kc], kh + 2);
            }
        }

        if (kt == qt) {   // diagonal tile mask
            int j0g = kt * 64, q0g = qt * NQ + wid * 16;
            int colb = t2 * 2, rowb = g4;
            #pragma unroll
            for (int nt = 0; nt < 8; nt++) {
                int jb = j0g + nt * 8 + colb;
                if (jb > q0g + rowb)          S[nt][0] = -1e30f;
                if (jb + 1 > q0g + rowb)      S[nt][1] = -1e30f;
                if (jb > q0g + rowb + 8)      S[nt][2] = -1e30f;
                if (jb + 1 > q0g + rowb + 8)  S[nt][3] = -1e30f;
            }
        }

        float mx0 = -1e30f, mx1 = -1e30f;
        #pragma unroll
        for (int nt = 0; nt < 8; nt++) {
            mx0 = fmaxf(mx0, fmaxf(S[nt][0], S[nt][1]));
            mx1 = fmaxf(mx1, fmaxf(S[nt][2], S[nt][3]));
        }
        mx0 = fmaxf(mx0, __shfl_xor_sync(0xffffffffu, mx0, 1));
        mx0 = fmaxf(mx0, __shfl_xor_sync(0xffffffffu, mx0, 2));
        mx1 = fmaxf(mx1, __shfl_xor_sync(0xffffffffu, mx1, 1));
        mx1 = fmaxf(mx1, __shfl_xor_sync(0xffffffffu, mx1, 2));
        float nm0 = fmaxf(m0, mx0), nm1 = fmaxf(m1, mx1);
        float a0 = __expf(m0 - nm0), a1 = __expf(m1 - nm1);
        m0 = nm0; m1 = nm1;

        float rs0 = 0.f, rs1 = 0.f;
        uint32_t phA[8], phB[8], plA[8], plB[8];
        #pragma unroll
        for (int nt = 0; nt < 8; nt++) {
            float p0 = __expf(S[nt][0] - nm0), p1 = __expf(S[nt][1] - nm0);
            float p2 = __expf(S[nt][2] - nm1), p3 = __expf(S[nt][3] - nm1);
            rs0 += p0 + p1; rs1 += p2 + p3;
            split_pack(p0, p1, phA[nt], plA[nt]);
            split_pack(p2, p3, phB[nt], plB[nt]);
        }
        rs0 += __shfl_xor_sync(0xffffffffu, rs0, 1);
        rs0 += __shfl_xor_sync(0xffffffffu, rs0, 2);
        rs1 += __shfl_xor_sync(0xffffffffu, rs1, 1);
        rs1 += __shfl_xor_sync(0xffffffffu, rs1, 2);
        l0 = l0 * a0 + rs0;
        l1 = l1 * a1 + rs1;
        #pragma unroll
        for (int dt = 0; dt < 8; dt++) {
            accO[dt][0] *= a0; accO[dt][1] *= a0;
            accO[dt][2] *= a1; accO[dt][3] *= a1;
        }

        uint32_t vb = sb + 2 * KVTILE;
        #pragma unroll
        for (int kc = 0; kc < 4; kc++) {
            uint32_t aph[4] = {phA[2 * kc], phB[2 * kc], phA[2 * kc + 1], phB[2 * kc + 1]};
            uint32_t apl[4] = {plA[2 * kc], plB[2 * kc], plA[2 * kc + 1], plB[2 * kc + 1]};
            #pragma unroll
            for (int d0t = 0; d0t < 4; d0t++) {
                uint32_t va = vb + (kc * 16) * PITCHB + d0t * 32 + vfo;
                uint32_t vh[4], vl[4];
                ldmatrix_x4t(vh, va);
                ldmatrix_x4t(vl, va + KVTILE);
                mma16816(accO[2 * d0t], aph, vh);
                mma16816(accO[2 * d0t], apl, vh);
                mma16816(accO[2 * d0t], aph, vl);
                mma16816(accO[2 * d0t + 1], aph, vh + 2);
                mma16816(accO[2 * d0t + 1], apl, vh + 2);
                mma16816(accO[2 * d0t + 1], aph, vl + 2);
            }
        }

        __syncthreads();
        if (kt + 2 < nkt) load_kv(kt + 2, kt & 1);
        CP_COMMIT();
        CP_WAIT1();
        __syncthreads();
    }

    float inv0 = 1.0f / l0, inv1 = 1.0f / l1;
    int b = bh >> 4, h = bh & 15;
    int s0 = qt * NQ + wid * 16 + g4, s1 = s0 + 8;
    size_t r0o = ((size_t)(b * Sv + s0)) * Ev + h * 64;
    size_t r1o = ((size_t)(b * Sv + s1)) * Ev + h * 64;
    #pragma unroll
    for (int dt = 0; dt < 8; dt++) {
        int d = dt * 8 + t2 * 2;
        uint32_t hw, lw;
        split_pack(accO[dt][0] * inv0, accO[dt][1] * inv0, hw, lw);
        *(uint32_t*)&Ohi[r0o + d] = hw;
        *(uint32_t*)&Olo[r0o + d] = lw;
        split_pack(accO[dt][2] * inv1, accO[dt][3] * inv1, hw, lw);
        *(uint32_t*)&Ohi[r1o + d] = hw;
        *(uint32_t*)&Olo[r1o + d] = lw;
    }
}

// ---------------------------------------------------------------------------
extern "C" void kernel_launch(void* const* d_in, const int* in_sizes, int n_in,
                              void* d_out, int out_size)
{
    const float* x  = (const float*)d_in[0];
    const float* wq = (const float*)d_in[1];
    const float* bq = (const float*)d_in[2];
    const float* wk = (const float*)d_in[3];
    const float* bk = (const float*)d_in[4];
    const float* wv = (const float*)d_in[5];
    const float* bv = (const float*)d_in[6];
    const float* wo = (const float*)d_in[7];
    const float* bo = (const float*)d_in[8];
    float* out = (float*)d_out;

    cudaFuncSetAttribute(gemm_qkv_kernel,
                         cudaFuncAttributeMaxDynamicSharedMemorySize, GEMM_SMEM);
    cudaFuncSetAttribute(gemm_final_kernel,
                         cudaFuncAttributeMaxDynamicSharedMemorySize, GEMM_SMEM);
    cudaFuncSetAttribute(attn_mma_kernel,
                         cudaFuncAttributeMaxDynamicSharedMemorySize, ATTN_SMEM);

    __nv_bfloat16 *qhi, *qlo, *khi, *klo, *vhi, *vlo;
    __nv_bfloat16 *xhi, *xlo, *ohi, *olo;
    __nv_bfloat16 *wqhi, *wqlo, *wkhi, *wklo, *wvhi, *wvlo, *wohi, *wolo;
    cudaGetSymbolAddress((void**)&qhi, g_Qhi);
    cudaGetSymbolAddress((void**)&qlo, g_Qlo);
    cudaGetSymbolAddress((void**)&khi, g_Khi);
    cudaGetSymbolAddress((void**)&klo, g_Klo);
    cudaGetSymbolAddress((void**)&vhi, g_Vhi);
    cudaGetSymbolAddress((void**)&vlo, g_Vlo);
    cudaGetSymbolAddress((void**)&xhi, g_xhi);
    cudaGetSymbolAddress((void**)&xlo, g_xlo);
    cudaGetSymbolAddress((void**)&ohi, g_ohi);
    cudaGetSymbolAddress((void**)&olo, g_olo);
    cudaGetSymbolAddress((void**)&wqhi, g_wqhi);
    cudaGetSymbolAddress((void**)&wqlo, g_wqlo);
    cudaGetSymbolAddress((void**)&wkhi, g_wkhi);
    cudaGetSymbolAddress((void**)&wklo, g_wklo);
    cudaGetSymbolAddress((void**)&wvhi, g_wvhi);
    cudaGetSymbolAddress((void**)&wvlo, g_wvlo);
    cudaGetSymbolAddress((void**)&wohi, g_wohi);
    cudaGetSymbolAddress((void**)&wolo, g_wolo);

    const int NX = Mtot * Ev;
    const int NW = Ev * Ev;
    split_bf16_kernel<<<NX / 1024, 256>>>(x, xhi, xlo);
    split4_kernel<<<dim3(NW / 1024, 4), 256>>>(
        wq, wk, wv, wo,
        wqhi, wqlo, wkhi, wklo, wvhi, wvlo, wohi, wolo);

    gemm_qkv_kernel<<<dim3(Ev / 256, Mtot / 128, 3), 256, GEMM_SMEM>>>(
        xhi, xlo, wqhi, wqlo, wkhi, wklo, wvhi, wvlo,
        bq, bk, bv, qhi, qlo, khi, klo, vhi, vlo);

    attn_mma_kernel<<<dim3(Sv / NQ, Bv * Hv), 128, ATTN_SMEM>>>(
        qhi, qlo, khi, klo, vhi, vlo, ohi, olo);

    gemm_final_kernel<<<dim3(Ev / 256, Mtot / 128), 256, GEMM_SMEM>>>(
        ohi, olo, wohi, wolo, bo, out);
}

// round 10
// speedup vs baseline: 1.0272x; 1.0272x over previous
#include <cuda_runtime.h>
#include <cuda_bf16.h>
#include <cstdint>
#include <math.h>

#define Bv 2
#define Sv 2048
#define Ev 1024
#define Hv 16
#define Dv 64
#define Mtot (Bv * Sv)          // 4096

enum { MODE_ROPEQ = 0, MODE_ROPEK = 1, MODE_BHSD = 2, MODE_PLAIN = 3 };

// ---------------- scratch (__device__ globals; no allocs allowed) ----------
__device__ __nv_bfloat16 g_Qhi[Bv * Hv * Sv * Dv], g_Qlo[Bv * Hv * Sv * Dv];
__device__ __nv_bfloat16 g_Khi[Bv * Hv * Sv * Dv], g_Klo[Bv * Hv * Sv * Dv];
__device__ __nv_bfloat16 g_Vhi[Bv * Hv * Sv * Dv], g_Vlo[Bv * Hv * Sv * Dv];
__device__ __nv_bfloat16 g_xhi[Mtot * Ev], g_xlo[Mtot * Ev];
__device__ __nv_bfloat16 g_ohi[Mtot * Ev], g_olo[Mtot * Ev];
__device__ __nv_bfloat16 g_wqhi[Ev * Ev], g_wqlo[Ev * Ev];
__device__ __nv_bfloat16 g_wkhi[Ev * Ev], g_wklo[Ev * Ev];
__device__ __nv_bfloat16 g_wvhi[Ev * Ev], g_wvlo[Ev * Ev];
__device__ __nv_bfloat16 g_wohi[Ev * Ev], g_wolo[Ev * Ev];

// ---------------- helpers --------------------------------------------------
__device__ __forceinline__ uint32_t smem_to_u32(const void* p) {
    uint32_t a;
    asm("{ .reg .u64 t; cvta.to.shared.u64 t, %1; cvt.u32.u64 %0, t; }"
        : "=r"(a) : "l"(p));
    return a;
}

__device__ __forceinline__ void ldmatrix_x4(uint32_t* r, uint32_t addr) {
    asm volatile("ldmatrix.sync.aligned.m8n8.x4.shared.b16 {%0,%1,%2,%3}, [%4];"
                 : "=r"(r[0]), "=r"(r[1]), "=r"(r[2]), "=r"(r[3]) : "r"(addr));
}
__device__ __forceinline__ void ldmatrix_x4t(uint32_t* r, uint32_t addr) {
    asm volatile("ldmatrix.sync.aligned.m8n8.x4.trans.shared.b16 {%0,%1,%2,%3}, [%4];"
                 : "=r"(r[0]), "=r"(r[1]), "=r"(r[2]), "=r"(r[3]) : "r"(addr));
}

__device__ __forceinline__ void mma16816(float* c, const uint32_t* a,
                                         const uint32_t* b) {
    asm volatile(
        "mma.sync.aligned.m16n8k16.row.col.f32.bf16.bf16.f32 "
        "{%0,%1,%2,%3}, {%4,%5,%6,%7}, {%8,%9}, {%0,%1,%2,%3};"
        : "+f"(c[0]), "+f"(c[1]), "+f"(c[2]), "+f"(c[3])
        : "r"(a[0]), "r"(a[1]), "r"(a[2]), "r"(a[3]), "r"(b[0]), "r"(b[1]));
}

#define CP_ASYNC16(smem, gptr) \
    asm volatile("cp.async.cg.shared.global [%0], [%1], 16;" \
                 :: "r"(smem), "l"(gptr))
#define CP_COMMIT() asm volatile("cp.async.commit_group;" ::: "memory")
#define CP_WAIT1()  asm volatile("cp.async.wait_group 1;" ::: "memory")

// sincos accurate under --use_fast_math (Cody-Waite 2*pi reduction)
__device__ __forceinline__ void sincos_red(float ang, float* s, float* c) {
    float kf = rintf(ang * 0.15915494309189535f);
    float r = fmaf(kf, -6.2831854820251465f, ang);
    r = fmaf(kf, 1.7484555e-7f, r);
    __sincosf(r, s, c);
}

// split two fp32 into packed bf16x2 (hi) + packed bf16x2 (residual lo)
__device__ __forceinline__ void split_pack(float p0, float p1,
                                           uint32_t& hi, uint32_t& lo) {
    __nv_bfloat16 h0 = __float2bfloat16(p0), h1 = __float2bfloat16(p1);
    float r0 = p0 - __bfloat162float(h0), r1 = p1 - __bfloat162float(h1);
    __nv_bfloat162 hp; hp.x = h0; hp.y = h1;
    __nv_bfloat162 lp; lp.x = __float2bfloat16(r0); lp.y = __float2bfloat16(r1);
    hi = *(uint32_t*)&hp; lo = *(uint32_t*)&lp;
}

// ---------------------------------------------------------------------------
// fp32 -> (hi, lo) bf16 splits
// ---------------------------------------------------------------------------
__global__ __launch_bounds__(256)
void split_bf16_kernel(const float* __restrict__ src,
                       __nv_bfloat16* __restrict__ hi,
                       __nv_bfloat16* __restrict__ lo)
{
    int i = (blockIdx.x * 256 + threadIdx.x) * 4;
    float4 v = *(const float4*)(src + i);
    uint32_t hA, lA, hB, lB;
    split_pack(v.x, v.y, hA, lA);
    split_pack(v.z, v.w, hB, lB);
    *(uint32_t*)&hi[i]     = hA;
    *(uint32_t*)&hi[i + 2] = hB;
    *(uint32_t*)&lo[i]     = lA;
    *(uint32_t*)&lo[i + 2] = lB;
}

__global__ __launch_bounds__(256)
void split4_kernel(const float* __restrict__ w0, const float* __restrict__ w1,
                   const float* __restrict__ w2, const float* __restrict__ w3,
                   __nv_bfloat16* __restrict__ h0, __nv_bfloat16* __restrict__ l0,
                   __nv_bfloat16* __restrict__ h1, __nv_bfloat16* __restrict__ l1,
                   __nv_bfloat16* __restrict__ h2, __nv_bfloat16* __restrict__ l2,
                   __nv_bfloat16* __restrict__ h3, __nv_bfloat16* __restrict__ l3)
{
    int y = blockIdx.y;
    const float* src = (y == 0) ? w0 : (y == 1) ? w1 : (y == 2) ? w2 : w3;
    __nv_bfloat16* hi = (y == 0) ? h0 : (y == 1) ? h1 : (y == 2) ? h2 : h3;
    __nv_bfloat16* lo = (y == 0) ? l0 : (y == 1) ? l1 : (y == 2) ? l2 : l3;
    int i = (blockIdx.x * 256 + threadIdx.x) * 4;
    float4 v = *(const float4*)(src + i);
    uint32_t hA, lA, hB, lB;
    split_pack(v.x, v.y, hA, lA);
    split_pack(v.z, v.w, hB, lB);
    *(uint32_t*)&hi[i]     = hA;
    *(uint32_t*)&hi[i + 2] = hB;
    *(uint32_t*)&lo[i]     = lA;
    *(uint32_t*)&lo[i + 2] = lB;
}

// ---------------------------------------------------------------------------
// bf16x3 GEMM core via mma.sync: C[m,n] = sum_k A[m,k]*W[n,k] + bias[n].
// CTA: 128x128 tile, 8 warps (2x4), warp tile 64x32, K-chunks of 32.
// 2-stage cp.async pipeline, 2 CTAs/SM (16 warps/SM for latency hiding).
// ---------------------------------------------------------------------------
#define GBK 32
#define GNCHUNK (Ev / GBK)               // 32
#define GT 10240                         // one 128-row tile (80B pitch)
#define GSTAGE (4 * GT)                  // 40960
#define GEMM_SMEM (2 * GSTAGE + 256)     // 82176

__device__ __forceinline__
void gemm_core(const __nv_bfloat16* __restrict__ Ahi,
               const __nv_bfloat16* __restrict__ Alo,
               const __nv_bfloat16* __restrict__ Whi,
               const __nv_bfloat16* __restrict__ Wlo,
               const float* __restrict__ bias,
               float* __restrict__ dstf,
               __nv_bfloat16* __restrict__ dsthi,
               __nv_bfloat16* __restrict__ dstlo, int mode)
{
    extern __shared__ char dsm[];
    uint32_t base = (smem_to_u32(dsm) + 127) & ~127u;

    const int tid = threadIdx.x;
    const int wid = tid >> 5, lid = tid & 31;
    const int wm = wid >> 2, wn = wid & 3;       // 2x4 warp grid
    const int m0 = blockIdx.y * 128, n0 = blockIdx.x * 128;

    const __nv_bfloat16* srcs[4] = {
        Ahi + (size_t)m0 * Ev, Alo + (size_t)m0 * Ev,
        Whi + (size_t)n0 * Ev, Wlo + (size_t)n0 * Ev };

    auto load_chunk = [&](int c, int s) {
        const int k0 = c * GBK;
        uint32_t sb = base + s * GSTAGE;
        #pragma unroll
        for (int it = 0; it < 8; it++) {
            int e = it * 256 + tid;
            int c16 = e & 3;
            int grow = e >> 2;                  // 0..511
            int tile = grow >> 7, row = grow & 127;
            uint32_t so = sb + tile * GT + row * 80 + c16 * 16;
            const void* g = srcs[tile] + (size_t)row * Ev + k0 + c16 * 8;
            CP_ASYNC16(so, g);
        }
    };

    float acc[4][4][4] = {};

    const uint32_t aoff = (lid & 15) * 80 + (lid >> 4) * 16;
    const uint32_t boff = ((lid >> 4) * 8 + (lid & 7)) * 80 + ((lid >> 3) & 1) * 16;

    load_chunk(0, 0);
    CP_COMMIT();

    for (int c = 0; c < GNCHUNK; c++) {
        if (c + 1 < GNCHUNK) load_chunk(c + 1, (c + 1) & 1);
        CP_COMMIT();
        CP_WAIT1();
        __syncthreads();

        uint32_t sb  = base + (c & 1) * GSTAGE;
        uint32_t aHI = sb + (wm * 64) * 80;
        uint32_t aLO = aHI + GT;
        uint32_t bHI = sb + 2 * GT + (wn * 32) * 80;
        uint32_t bLO = bHI + GT;

        #pragma unroll
        for (int ks = 0; ks < 2; ks++) {
            uint32_t kb = ks * 32;
            // B-hi fragments (4 nt)
            uint32_t bh[4][2];
            #pragma unroll
            for (int pr = 0; pr < 2; pr++) {
                uint32_t t4[4];
                ldmatrix_x4(t4, bHI + pr * (16 * 80) + kb + boff);
                bh[2 * pr][0] = t4[0]; bh[2 * pr][1] = t4[1];
                bh[2 * pr + 1][0] = t4[2]; bh[2 * pr + 1][1] = t4[3];
            }
            // term 1: ah*bh
            uint32_t ah[4][4];
            #pragma unroll
            for (int mt = 0; mt < 4; mt++)
                ldmatrix_x4(ah[mt], aHI + mt * (16 * 80) + kb + aoff);
            #pragma unroll
            for (int mt = 0; mt < 4; mt++)
                #pragma unroll
                for (int nt = 0; nt < 4; nt++)
                    mma16816(acc[mt][nt], ah[mt], bh[nt]);
            // term 2: al*bh
            {
                uint32_t al[4][4];
                #pragma unroll
                for (int mt = 0; mt < 4; mt++)
                    ldmatrix_x4(al[mt], aLO + mt * (16 * 80) + kb + aoff);
                #pragma unroll
                for (int mt = 0; mt < 4; mt++)
                    #pragma unroll
                    for (int nt = 0; nt < 4; nt++)
                        mma16816(acc[mt][nt], al[mt], bh[nt]);
            }
            // term 3: ah*bl
            {
                uint32_t bl[4][2];
                #pragma unroll
                for (int pr = 0; pr < 2; pr++) {
                    uint32_t t4[4];
                    ldmatrix_x4(t4, bLO + pr * (16 * 80) + kb + boff);
                    bl[2 * pr][0] = t4[0]; bl[2 * pr][1] = t4[1];
                    bl[2 * pr + 1][0] = t4[2]; bl[2 * pr + 1][1] = t4[3];
                }
                #pragma unroll
                for (int mt = 0; mt < 4; mt++)
                    #pragma unroll
                    for (int nt = 0; nt < 4; nt++)
                        mma16816(acc[mt][nt], ah[mt], bl[nt]);
            }
        }
        __syncthreads();
    }

    // ------------------- epilogue -------------------
    const int g4 = lid >> 2, t2 = lid & 3;
    #pragma unroll
    for (int nt = 0; nt < 4; nt++) {
        int n = n0 + wn * 32 + nt * 8 + t2 * 2;
        float bi0 = bias[n], bi1 = bias[n + 1];
        int h = n >> 6, d = n & 63;
        float fe = 0.f, fo = 0.f;
        if (mode == MODE_ROPEQ || mode == MODE_ROPEK) {
            fe = powf(10000.0f, -(float)(2 * (d & 31)) / 64.0f);
            fo = powf(10000.0f, -(float)(2 * ((d + 1) & 31)) / 64.0f);
        }
        #pragma unroll
        for (int mt = 0; mt < 4; mt++) {
            #pragma unroll
            for (int hf = 0; hf < 2; hf++) {
                int m = m0 + wm * 64 + mt * 16 + g4 + hf * 8;
                float v0 = acc[mt][nt][hf * 2 + 0] + bi0;
                float v1 = acc[mt][nt][hf * 2 + 1] + bi1;
                if (mode == MODE_PLAIN) {
                    float2 o = {v0, v1};
                    *(float2*)&dstf[(size_t)m * Ev + n] = o;
                } else {
                    int b = m >> 11, srow = m & 2047;
                    if (mode != MODE_BHSD) {
                        float pos = (float)srow;
                        float se, ce, so, co;
                        sincos_red(pos * fe, &se, &ce);
                        sincos_red(pos * fo, &so, &co);
                        float r0 = v0 * ce - v1 * se;
                        float r1 = v1 * co + v0 * so;
                        v0 = r0; v1 = r1;
                        if (mode == MODE_ROPEQ) { v0 *= 0.125f; v1 *= 0.125f; }
                    }
                    uint32_t hw, lw;
                    split_pack(v0, v1, hw, lw);
                    size_t off = (((size_t)(b * Hv + h) * Sv + srow) << 6) + d;
                    *(uint32_t*)&dsthi[off] = hw;
                    *(uint32_t*)&dstlo[off] = lw;
                }
            }
        }
    }
}

__global__ __launch_bounds__(256, 2)
void gemm_qkv_kernel(const __nv_bfloat16* __restrict__ xhi,
                     const __nv_bfloat16* __restrict__ xlo,
                     const __nv_bfloat16* __restrict__ wqhi, const __nv_bfloat16* __restrict__ wqlo,
                     const __nv_bfloat16* __restrict__ wkhi, const __nv_bfloat16* __restrict__ wklo,
                     const __nv_bfloat16* __restrict__ wvhi, const __nv_bfloat16* __restrict__ wvlo,
                     const float* __restrict__ bq, const float* __restrict__ bk,
                     const float* __restrict__ bv,
                     __nv_bfloat16* __restrict__ qhi, __nv_bfloat16* __restrict__ qlo,
                     __nv_bfloat16* __restrict__ khi, __nv_bfloat16* __restrict__ klo,
                     __nv_bfloat16* __restrict__ vhi, __nv_bfloat16* __restrict__ vlo)
{
    int z = blockIdx.z;
    const __nv_bfloat16* whi = (z == 0) ? wqhi : (z == 1) ? wkhi : wvhi;
    const __nv_bfloat16* wlo = (z == 0) ? wqlo : (z == 1) ? wklo : wvlo;
    const float* bias = (z == 0) ? bq : (z == 1) ? bk : bv;
    __nv_bfloat16* dhi = (z == 0) ? qhi : (z == 1) ? khi : vhi;
    __nv_bfloat16* dlo = (z == 0) ? qlo : (z == 1) ? klo : vlo;
    int mode = (z == 0) ? MODE_ROPEQ : (z == 1) ? MODE_ROPEK : MODE_BHSD;
    gemm_core(xhi, xlo, whi, wlo, bias, nullptr, dhi, dlo, mode);
}

__global__ __launch_bounds__(256, 2)
void gemm_final_kernel(const __nv_bfloat16* __restrict__ ohi,
                       const __nv_bfloat16* __restrict__ olo,
                       const __nv_bfloat16* __restrict__ wohi,
                       const __nv_bfloat16* __restrict__ wolo,
                       const float* __restrict__ bo, float* __restrict__ out)
{
    gemm_core(ohi, olo, wohi, wolo, bo, out, nullptr, nullptr, MODE_PLAIN);
}

// ---------------------------------------------------------------------------
// Flash attention via mma.sync, bf16x3, SOFTWARE-PIPELINED S:
// at tile kt, S-MMAs for tile kt+1 are issued BEFORE softmax(kt)+PV(kt),
// so the tensor pipe stays busy while the warp runs softmax ALU work.
// CTA = 64 queries (4 warps), 3 KV stages (prefetch distance 2), 2 CTAs/SM.
// Q is staged through stage-2's smem then recycled.
// ---------------------------------------------------------------------------
#define PITCHB 144
#define NQ 64
#define QSMB (NQ * PITCHB)           // 9216
#define KVTILE (64 * PITCHB)         // 9216
#define KVSTG (4 * KVTILE)           // 36864
#define ATTN_SMEM (3 * KVSTG)        // 110592

__global__ __launch_bounds__(128, 2)
void attn_mma_kernel(const __nv_bfloat16* __restrict__ Qhi,
                     const __nv_bfloat16* __restrict__ Qlo,
                     const __nv_bfloat16* __restrict__ Khi,
                     const __nv_bfloat16* __restrict__ Klo,
                     const __nv_bfloat16* __restrict__ Vhi,
                     const __nv_bfloat16* __restrict__ Vlo,
                     __nv_bfloat16* __restrict__ Ohi,
                     __nv_bfloat16* __restrict__ Olo)
{
    extern __shared__ char dsm[];
    uint32_t stg = smem_to_u32(dsm);
    const int tid = threadIdx.x, wid = tid >> 5, lid = tid & 31;
    const int qt = (int)gridDim.x - 1 - (int)blockIdx.x;  // longest first
    const int bh = blockIdx.y;
    const int nkt = qt + 1;
    const size_t bhb = (size_t)bh * Sv * 64;

    auto stage_addr = [&](int s) { return stg + (uint32_t)s * KVSTG; };

    auto load_kv = [&](int kt, int s) {
        uint32_t sb = stage_addr(s);
        const __nv_bfloat16* srcs[4] = {
            Khi + bhb + (size_t)kt * 64 * 64, Klo + bhb + (size_t)kt * 64 * 64,
            Vhi + bhb + (size_t)kt * 64 * 64, Vlo + bhb + (size_t)kt * 64 * 64 };
        #pragma unroll
        for (int it = 0; it < 16; it++) {
            int e = it * 128 + tid;
            int tl = e >> 9, r = (e >> 3) & 63, ch = e & 7;
            CP_ASYNC16(sb + tl * KVTILE + r * PITCHB + ch * 16,
                       srcs[tl] + r * 64 + ch * 8);
        }
    };

    // ---- prologue: Q -> stage2 region (temp), KV(0), KV(1) ----
    const uint32_t qtmp = stage_addr(2);
    {
        const __nv_bfloat16* gh = Qhi + bhb + (size_t)qt * NQ * 64;
        const __nv_bfloat16* gl = Qlo + bhb + (size_t)qt * NQ * 64;
        #pragma unroll
        for (int it = 0; it < 4; it++) {
            int e = it * 128 + tid;
            int r = e >> 3, ch = e & 7;
            CP_ASYNC16(qtmp + r * PITCHB + ch * 16, gh + r * 64 + ch * 8);
            CP_ASYNC16(qtmp + QSMB + r * PITCHB + ch * 16, gl + r * 64 + ch * 8);
        }
        load_kv(0, 0);
        CP_COMMIT();                 // G0 = Q + KV(0)
        if (nkt > 1) load_kv(1, 1);
        CP_COMMIT();                 // G1 = KV(1)
    }
    CP_WAIT1();                      // G0 done
    __syncthreads();

    // Q fragments (register resident)
    uint32_t qfh[4][4], qfl[4][4];
    {
        uint32_t qfo = (wid * 16 + (lid & 15)) * PITCHB + (lid >> 4) * 16;
        #pragma unroll
        for (int kc = 0; kc < 4; kc++) {
            ldmatrix_x4(qfh[kc], qtmp + qfo + kc * 32);
            ldmatrix_x4(qfl[kc], qtmp + QSMB + qfo + kc * 32);
        }
    }

    const uint32_t kfo = ((lid >> 4) * 8 + (lid & 7)) * PITCHB + ((lid >> 3) & 1) * 16;
    const uint32_t vfo = (lid & 15) * PITCHB + (lid >> 4) * 16;
    const int g4 = lid >> 2, t2 = lid & 3;

    auto compute_S = [&](float (&Sd)[8][4], int stage) {
        #pragma unroll
        for (int nt = 0; nt < 8; nt++)
            #pragma unroll
            for (int i = 0; i < 4; i++) Sd[nt][i] = 0.f;
        uint32_t sb = stage_addr(stage);
        #pragma unroll
        for (int kc = 0; kc < 4; kc++) {
            #pragma unroll
            for (int n0t = 0; n0t < 4; n0t++) {
                uint32_t ka = sb + (n0t * 16) * PITCHB + kc * 32 + kfo;
                uint32_t kh[4], kl[4];
                ldmatrix_x4(kh, ka);
                ldmatrix_x4(kl, ka + KVTILE);
                mma16816(Sd[2 * n0t], qfh[kc], kh);
                mma16816(Sd[2 * n0t], qfh[kc], kl);
                mma16816(Sd[2 * n0t], qfl[kc], kh);
                mma16816(Sd[2 * n0t + 1], qfh[kc], kh + 2);
                mma16816(Sd[2 * n0t + 1], qfh[kc], kl + 2);
                mma16816(Sd[2 * n0t + 1], qfl[kc], kh + 2);
            }
        }
    };

    float SA[8][4], SB[8][4];
    compute_S(SA, 0);                // S(0) while stage1/2 loads fly

    __syncthreads();                 // Q region free -> reuse as stage2
    if (nkt > 2) load_kv(2, 2);
    CP_COMMIT();                     // G2
    CP_WAIT1();                      // G1 done (stage1 ready)
    __syncthreads();

    float m0 = -1e30f, m1 = -1e30f, l0 = 0.f, l1 = 0.f;
    float accO[8][4] = {};

    auto body = [&](float (&Scur)[8][4], float (&Snext)[8][4], int kt) {
        // ---- prefetch S for kt+1: tensor pipe busy during softmax below ----
        if (kt + 1 < nkt) compute_S(Snext, (kt + 1) % 3);

        // ---- causal mask (diagonal tile only) ----
        if (kt == qt) {
            int j0g = kt * 64, q0g = qt * NQ + wid * 16;
            int colb = t2 * 2, rowb = g4;
            #pragma unroll
            for (int nt = 0; nt < 8; nt++) {
                int jb = j0g + nt * 8 + colb;
                if (jb > q0g + rowb)          Scur[nt][0] = -1e30f;
                if (jb + 1 > q0g + rowb)      Scur[nt][1] = -1e30f;
                if (jb > q0g + rowb + 8)      Scur[nt][2] = -1e30f;
                if (jb + 1 > q0g + rowb + 8)  Scur[nt][3] = -1e30f;
            }
        }

        // ---- online softmax ----
        float mx0 = -1e30f, mx1 = -1e30f;
        #pragma unroll
        for (int nt = 0; nt < 8; nt++) {
            mx0 = fmaxf(mx0, fmaxf(Scur[nt][0], Scur[nt][1]));
            mx1 = fmaxf(mx1, fmaxf(Scur[nt][2], Scur[nt][3]));
        }
        mx0 = fmaxf(mx0, __shfl_xor_sync(0xffffffffu, mx0, 1));
        mx0 = fmaxf(mx0, __shfl_xor_sync(0xffffffffu, mx0, 2));
        mx1 = fmaxf(mx1, __shfl_xor_sync(0xffffffffu, mx1, 1));
        mx1 = fmaxf(mx1, __shfl_xor_sync(0xffffffffu, mx1, 2));
        float nm0 = fmaxf(m0, mx0), nm1 = fmaxf(m1, mx1);
        float a0 = __expf(m0 - nm0), a1 = __expf(m1 - nm1);
        m0 = nm0; m1 = nm1;

        float rs0 = 0.f, rs1 = 0.f;
        uint32_t phA[8], phB[8], plA[8], plB[8];
        #pragma unroll
        for (int nt = 0; nt < 8; nt++) {
            float p0 = __expf(Scur[nt][0] - nm0), p1 = __expf(Scur[nt][1] - nm0);
            float p2 = __expf(Scur[nt][2] - nm1), p3 = __expf(Scur[nt][3] - nm1);
            rs0 += p0 + p1; rs1 += p2 + p3;
            split_pack(p0, p1, phA[nt], plA[nt]);
            split_pack(p2, p3, phB[nt], plB[nt]);
        }
        rs0 += __shfl_xor_sync(0xffffffffu, rs0, 1);
        rs0 += __shfl_xor_sync(0xffffffffu, rs0, 2);
        rs1 += __shfl_xor_sync(0xffffffffu, rs1, 1);
        rs1 += __shfl_xor_sync(0xffffffffu, rs1, 2);
        l0 = l0 * a0 + rs0;
        l1 = l1 * a1 + rs1;
        #pragma unroll
        for (int dt = 0; dt < 8; dt++) {
            accO[dt][0] *= a0; accO[dt][1] *= a0;
            accO[dt][2] *= a1; accO[dt][3] *= a1;
        }

        // ---- O += P V (bf16x3) ----
        uint32_t vb = stage_addr(kt % 3) + 2 * KVTILE;
        #pragma unroll
        for (int kc = 0; kc < 4; kc++) {
            uint32_t aph[4] = {phA[2 * kc], phB[2 * kc], phA[2 * kc + 1], phB[2 * kc + 1]};
            uint32_t apl[4] = {plA[2 * kc], plB[2 * kc], plA[2 * kc + 1], plB[2 * kc + 1]};
            #pragma unroll
            for (int d0t = 0; d0t < 4; d0t++) {
                uint32_t va = vb + (kc * 16) * PITCHB + d0t * 32 + vfo;
                uint32_t vh[4], vl[4];
                ldmatrix_x4t(vh, va);
                ldmatrix_x4t(vl, va + KVTILE);
                mma16816(accO[2 * d0t], aph, vh);
                mma16816(accO[2 * d0t], apl, vh);
                mma16816(accO[2 * d0t], aph, vl);
                mma16816(accO[2 * d0t + 1], aph, vh + 2);
                mma16816(accO[2 * d0t + 1], apl, vh + 2);
                mma16816(accO[2 * d0t + 1], aph, vl + 2);
            }
        }

        // ---- pipeline wind: free stage kt%3, fetch kt+3 into it ----
        __syncthreads();
        if (kt + 3 < nkt) load_kv(kt + 3, kt % 3);
        CP_COMMIT();
        CP_WAIT1();                  // completes load(kt+2), needed next iter
        __syncthreads();
    };

    for (int kt = 0; kt < nkt; kt += 2) {
        body(SA, SB, kt);
        if (kt + 1 < nkt) body(SB, SA, kt + 1);
    }

    // ---- epilogue ----
    float inv0 = 1.0f / l0, inv1 = 1.0f / l1;
    int b = bh >> 4, h = bh & 15;
    int s0 = qt * NQ + wid * 16 + g4, s1 = s0 + 8;
    size_t r0o = ((size_t)(b * Sv + s0)) * Ev + h * 64;
    size_t r1o = ((size_t)(b * Sv + s1)) * Ev + h * 64;
    #pragma unroll
    for (int dt = 0; dt < 8; dt++) {
        int d = dt * 8 + t2 * 2;
        uint32_t hw, lw;
        split_pack(accO[dt][0] * inv0, accO[dt][1] * inv0, hw, lw);
        *(uint32_t*)&Ohi[r0o + d] = hw;
        *(uint32_t*)&Olo[r0o + d] = lw;
        split_pack(accO[dt][2] * inv1, accO[dt][3] * inv1, hw, lw);
        *(uint32_t*)&Ohi[r1o + d] = hw;
        *(uint32_t*)&Olo[r1o + d] = lw;
    }
}

// ---------------------------------------------------------------------------
extern "C" void kernel_launch(void* const* d_in, const int* in_sizes, int n_in,
                              void* d_out, int out_size)
{
    const float* x  = (const float*)d_in[0];
    const float* wq = (const float*)d_in[1];
    const float* bq = (const float*)d_in[2];
    const float* wk = (const float*)d_in[3];
    const float* bk = (const float*)d_in[4];
    const float* wv = (const float*)d_in[5];
    const float* bv = (const float*)d_in[6];
    const float* wo = (const float*)d_in[7];
    const float* bo = (const float*)d_in[8];
    float* out = (float*)d_out;

    cudaFuncSetAttribute(gemm_qkv_kernel,
                         cudaFuncAttributeMaxDynamicSharedMemorySize, GEMM_SMEM);
    cudaFuncSetAttribute(gemm_final_kernel,
                         cudaFuncAttributeMaxDynamicSharedMemorySize, GEMM_SMEM);
    cudaFuncSetAttribute(attn_mma_kernel,
                         cudaFuncAttributeMaxDynamicSharedMemorySize, ATTN_SMEM);

    __nv_bfloat16 *qhi, *qlo, *khi, *klo, *vhi, *vlo;
    __nv_bfloat16 *xhi, *xlo, *ohi, *olo;
    __nv_bfloat16 *wqhi, *wqlo, *wkhi, *wklo, *wvhi, *wvlo, *wohi, *wolo;
    cudaGetSymbolAddress((void**)&qhi, g_Qhi);
    cudaGetSymbolAddress((void**)&qlo, g_Qlo);
    cudaGetSymbolAddress((void**)&khi, g_Khi);
    cudaGetSymbolAddress((void**)&klo, g_Klo);
    cudaGetSymbolAddress((void**)&vhi, g_Vhi);
    cudaGetSymbolAddress((void**)&vlo, g_Vlo);
    cudaGetSymbolAddress((void**)&xhi, g_xhi);
    cudaGetSymbolAddress((void**)&xlo, g_xlo);
    cudaGetSymbolAddress((void**)&ohi, g_ohi);
    cudaGetSymbolAddress((void**)&olo, g_olo);
    cudaGetSymbolAddress((void**)&wqhi, g_wqhi);
    cudaGetSymbolAddress((void**)&wqlo, g_wqlo);
    cudaGetSymbolAddress((void**)&wkhi, g_wkhi);
    cudaGetSymbolAddress((void**)&wklo, g_wklo);
    cudaGetSymbolAddress((void**)&wvhi, g_wvhi);
    cudaGetSymbolAddress((void**)&wvlo, g_wvlo);
    cudaGetSymbolAddress((void**)&wohi, g_wohi);
    cudaGetSymbolAddress((void**)&wolo, g_wolo);

    const int NX = Mtot * Ev;
    const int NW = Ev * Ev;
    split_bf16_kernel<<<NX / 1024, 256>>>(x, xhi, xlo);
    split4_kernel<<<dim3(NW / 1024, 4), 256>>>(
        wq, wk, wv, wo,
        wqhi, wqlo, wkhi, wklo, wvhi, wvlo, wohi, wolo);

    gemm_qkv_kernel<<<dim3(Ev / 128, Mtot / 128, 3), 256, GEMM_SMEM>>>(
        xhi, xlo, wqhi, wqlo, wkhi, wklo, wvhi, wvlo,
        bq, bk, bv, qhi, qlo, khi, klo, vhi, vlo);

    attn_mma_kernel<<<dim3(Sv / NQ, Bv * Hv), 128, ATTN_SMEM>>>(
        qhi, qlo, khi, klo, vhi, vlo, ohi, olo);

    gemm_final_kernel<<<dim3(Ev / 128, Mtot / 128), 256, GEMM_SMEM>>>(
        ohi, olo, wohi, wolo, bo, out);
}

// round 11
// speedup vs baseline: 1.0303x; 1.0031x over previous
#include <cuda_runtime.h>
#include <cuda_bf16.h>
#include <cstdint>
#include <math.h>

#define Bv 2
#define Sv 2048
#define Ev 1024
#define Hv 16
#define Dv 64
#define Mtot (Bv * Sv)          // 4096

enum { MODE_ROPEQ = 0, MODE_ROPEK = 1, MODE_BHSD = 2, MODE_PLAIN = 3 };

// ---------------- scratch (__device__ globals; no allocs allowed) ----------
__device__ __nv_bfloat16 g_Qhi[Bv * Hv * Sv * Dv], g_Qlo[Bv * Hv * Sv * Dv];
__device__ __nv_bfloat16 g_Khi[Bv * Hv * Sv * Dv], g_Klo[Bv * Hv * Sv * Dv];
__device__ __nv_bfloat16 g_Vhi[Bv * Hv * Sv * Dv], g_Vlo[Bv * Hv * Sv * Dv];
__device__ __nv_bfloat16 g_xhi[Mtot * Ev], g_xlo[Mtot * Ev];
__device__ __nv_bfloat16 g_ohi[Mtot * Ev], g_olo[Mtot * Ev];
__device__ __nv_bfloat16 g_wqhi[Ev * Ev], g_wqlo[Ev * Ev];
__device__ __nv_bfloat16 g_wkhi[Ev * Ev], g_wklo[Ev * Ev];
__device__ __nv_bfloat16 g_wvhi[Ev * Ev], g_wvlo[Ev * Ev];
__device__ __nv_bfloat16 g_wohi[Ev * Ev], g_wolo[Ev * Ev];

// ---------------- helpers --------------------------------------------------
__device__ __forceinline__ uint32_t smem_to_u32(const void* p) {
    uint32_t a;
    asm("{ .reg .u64 t; cvta.to.shared.u64 t, %1; cvt.u32.u64 %0, t; }"
        : "=r"(a) : "l"(p));
    return a;
}

__device__ __forceinline__ void ldmatrix_x4(uint32_t* r, uint32_t addr) {
    asm volatile("ldmatrix.sync.aligned.m8n8.x4.shared.b16 {%0,%1,%2,%3}, [%4];"
                 : "=r"(r[0]), "=r"(r[1]), "=r"(r[2]), "=r"(r[3]) : "r"(addr));
}
__device__ __forceinline__ void ldmatrix_x4t(uint32_t* r, uint32_t addr) {
    asm volatile("ldmatrix.sync.aligned.m8n8.x4.trans.shared.b16 {%0,%1,%2,%3}, [%4];"
                 : "=r"(r[0]), "=r"(r[1]), "=r"(r[2]), "=r"(r[3]) : "r"(addr));
}

__device__ __forceinline__ void mma16816(float* c, const uint32_t* a,
                                         const uint32_t* b) {
    asm volatile(
        "mma.sync.aligned.m16n8k16.row.col.f32.bf16.bf16.f32 "
        "{%0,%1,%2,%3}, {%4,%5,%6,%7}, {%8,%9}, {%0,%1,%2,%3};"
        : "+f"(c[0]), "+f"(c[1]), "+f"(c[2]), "+f"(c[3])
        : "r"(a[0]), "r"(a[1]), "r"(a[2]), "r"(a[3]), "r"(b[0]), "r"(b[1]));
}

#define CP_ASYNC16(smem, gptr) \
    asm volatile("cp.async.cg.shared.global [%0], [%1], 16;" \
                 :: "r"(smem), "l"(gptr))
#define CP_COMMIT() asm volatile("cp.async.commit_group;" ::: "memory")
#define CP_WAIT1()  asm volatile("cp.async.wait_group 1;" ::: "memory")

// sincos accurate under --use_fast_math (Cody-Waite 2*pi reduction)
__device__ __forceinline__ void sincos_red(float ang, float* s, float* c) {
    float kf = rintf(ang * 0.15915494309189535f);
    float r = fmaf(kf, -6.2831854820251465f, ang);
    r = fmaf(kf, 1.7484555e-7f, r);
    __sincosf(r, s, c);
}

// split two fp32 into packed bf16x2 (hi) + packed bf16x2 (residual lo)
__device__ __forceinline__ void split_pack(float p0, float p1,
                                           uint32_t& hi, uint32_t& lo) {
    __nv_bfloat16 h0 = __float2bfloat16(p0), h1 = __float2bfloat16(p1);
    float r0 = p0 - __bfloat162float(h0), r1 = p1 - __bfloat162float(h1);
    __nv_bfloat162 hp; hp.x = h0; hp.y = h1;
    __nv_bfloat162 lp; lp.x = __float2bfloat16(r0); lp.y = __float2bfloat16(r1);
    hi = *(uint32_t*)&hp; lo = *(uint32_t*)&lp;
}

// ---------------------------------------------------------------------------
// fp32 -> (hi, lo) bf16 splits
// ---------------------------------------------------------------------------
__global__ __launch_bounds__(256)
void split_bf16_kernel(const float* __restrict__ src,
                       __nv_bfloat16* __restrict__ hi,
                       __nv_bfloat16* __restrict__ lo)
{
    int i = (blockIdx.x * 256 + threadIdx.x) * 4;
    float4 v = *(const float4*)(src + i);
    uint32_t hA, lA, hB, lB;
    split_pack(v.x, v.y, hA, lA);
    split_pack(v.z, v.w, hB, lB);
    *(uint32_t*)&hi[i]     = hA;
    *(uint32_t*)&hi[i + 2] = hB;
    *(uint32_t*)&lo[i]     = lA;
    *(uint32_t*)&lo[i + 2] = lB;
}

__global__ __launch_bounds__(256)
void split4_kernel(const float* __restrict__ w0, const float* __restrict__ w1,
                   const float* __restrict__ w2, const float* __restrict__ w3,
                   __nv_bfloat16* __restrict__ h0, __nv_bfloat16* __restrict__ l0,
                   __nv_bfloat16* __restrict__ h1, __nv_bfloat16* __restrict__ l1,
                   __nv_bfloat16* __restrict__ h2, __nv_bfloat16* __restrict__ l2,
                   __nv_bfloat16* __restrict__ h3, __nv_bfloat16* __restrict__ l3)
{
    int y = blockIdx.y;
    const float* src = (y == 0) ? w0 : (y == 1) ? w1 : (y == 2) ? w2 : w3;
    __nv_bfloat16* hi = (y == 0) ? h0 : (y == 1) ? h1 : (y == 2) ? h2 : h3;
    __nv_bfloat16* lo = (y == 0) ? l0 : (y == 1) ? l1 : (y == 2) ? l2 : l3;
    int i = (blockIdx.x * 256 + threadIdx.x) * 4;
    float4 v = *(const float4*)(src + i);
    uint32_t hA, lA, hB, lB;
    split_pack(v.x, v.y, hA, lA);
    split_pack(v.z, v.w, hB, lB);
    *(uint32_t*)&hi[i]     = hA;
    *(uint32_t*)&hi[i + 2] = hB;
    *(uint32_t*)&lo[i]     = lA;
    *(uint32_t*)&lo[i + 2] = lB;
}

// ---------------------------------------------------------------------------
// bf16x3 GEMM core via mma.sync: C[m,n] = sum_k A[m,k]*W[n,k] + bias[n].
// CTA: 128x128 tile, 8 warps (2x4), warp tile 64x32, K-chunks of 32.
// 2-stage cp.async pipeline, 2 CTAs/SM. Term-ordered (independent) MMAs.
// ---------------------------------------------------------------------------
#define GBK 32
#define GNCHUNK (Ev / GBK)               // 32
#define GT 10240                         // one 128-row tile (80B pitch)
#define GSTAGE (4 * GT)                  // 40960
#define GEMM_SMEM (2 * GSTAGE + 256)     // 82176

__device__ __forceinline__
void gemm_core(const __nv_bfloat16* __restrict__ Ahi,
               const __nv_bfloat16* __restrict__ Alo,
               const __nv_bfloat16* __restrict__ Whi,
               const __nv_bfloat16* __restrict__ Wlo,
               const float* __restrict__ bias,
               float* __restrict__ dstf,
               __nv_bfloat16* __restrict__ dsthi,
               __nv_bfloat16* __restrict__ dstlo, int mode)
{
    extern __shared__ char dsm[];
    uint32_t base = (smem_to_u32(dsm) + 127) & ~127u;

    const int tid = threadIdx.x;
    const int wid = tid >> 5, lid = tid & 31;
    const int wm = wid >> 2, wn = wid & 3;       // 2x4 warp grid
    const int m0 = blockIdx.y * 128, n0 = blockIdx.x * 128;

    const __nv_bfloat16* srcs[4] = {
        Ahi + (size_t)m0 * Ev, Alo + (size_t)m0 * Ev,
        Whi + (size_t)n0 * Ev, Wlo + (size_t)n0 * Ev };

    auto load_chunk = [&](int c, int s) {
        const int k0 = c * GBK;
        uint32_t sb = base + s * GSTAGE;
        #pragma unroll
        for (int it = 0; it < 8; it++) {
            int e = it * 256 + tid;
            int c16 = e & 3;
            int grow = e >> 2;                  // 0..511
            int tile = grow >> 7, row = grow & 127;
            uint32_t so = sb + tile * GT + row * 80 + c16 * 16;
            const void* g = srcs[tile] + (size_t)row * Ev + k0 + c16 * 8;
            CP_ASYNC16(so, g);
        }
    };

    float acc[4][4][4] = {};

    const uint32_t aoff = (lid & 15) * 80 + (lid >> 4) * 16;
    const uint32_t boff = ((lid >> 4) * 8 + (lid & 7)) * 80 + ((lid >> 3) & 1) * 16;

    load_chunk(0, 0);
    CP_COMMIT();

    for (int c = 0; c < GNCHUNK; c++) {
        if (c + 1 < GNCHUNK) load_chunk(c + 1, (c + 1) & 1);
        CP_COMMIT();
        CP_WAIT1();
        __syncthreads();

        uint32_t sb  = base + (c & 1) * GSTAGE;
        uint32_t aHI = sb + (wm * 64) * 80;
        uint32_t aLO = aHI + GT;
        uint32_t bHI = sb + 2 * GT + (wn * 32) * 80;
        uint32_t bLO = bHI + GT;

        #pragma unroll
        for (int ks = 0; ks < 2; ks++) {
            uint32_t kb = ks * 32;
            // B-hi fragments (4 nt)
            uint32_t bh[4][2];
            #pragma unroll
            for (int pr = 0; pr < 2; pr++) {
                uint32_t t4[4];
                ldmatrix_x4(t4, bHI + pr * (16 * 80) + kb + boff);
                bh[2 * pr][0] = t4[0]; bh[2 * pr][1] = t4[1];
                bh[2 * pr + 1][0] = t4[2]; bh[2 * pr + 1][1] = t4[3];
            }
            // term 1: ah*bh
            uint32_t ah[4][4];
            #pragma unroll
            for (int mt = 0; mt < 4; mt++)
                ldmatrix_x4(ah[mt], aHI + mt * (16 * 80) + kb + aoff);
            #pragma unroll
            for (int mt = 0; mt < 4; mt++)
                #pragma unroll
                for (int nt = 0; nt < 4; nt++)
                    mma16816(acc[mt][nt], ah[mt], bh[nt]);
            // term 2: al*bh
            {
                uint32_t al[4][4];
                #pragma unroll
                for (int mt = 0; mt < 4; mt++)
                    ldmatrix_x4(al[mt], aLO + mt * (16 * 80) + kb + aoff);
                #pragma unroll
                for (int mt = 0; mt < 4; mt++)
                    #pragma unroll
                    for (int nt = 0; nt < 4; nt++)
                        mma16816(acc[mt][nt], al[mt], bh[nt]);
            }
            // term 3: ah*bl
            {
                uint32_t bl[4][2];
                #pragma unroll
                for (int pr = 0; pr < 2; pr++) {
                    uint32_t t4[4];
                    ldmatrix_x4(t4, bLO + pr * (16 * 80) + kb + boff);
                    bl[2 * pr][0] = t4[0]; bl[2 * pr][1] = t4[1];
                    bl[2 * pr + 1][0] = t4[2]; bl[2 * pr + 1][1] = t4[3];
                }
                #pragma unroll
                for (int mt = 0; mt < 4; mt++)
                    #pragma unroll
                    for (int nt = 0; nt < 4; nt++)
                        mma16816(acc[mt][nt], ah[mt], bl[nt]);
            }
        }
        __syncthreads();
    }

    // ------------------- epilogue -------------------
    const int g4 = lid >> 2, t2 = lid & 3;
    #pragma unroll
    for (int nt = 0; nt < 4; nt++) {
        int n = n0 + wn * 32 + nt * 8 + t2 * 2;
        float bi0 = bias[n], bi1 = bias[n + 1];
        int h = n >> 6, d = n & 63;
        float fe = 0.f, fo = 0.f;
        if (mode == MODE_ROPEQ || mode == MODE_ROPEK) {
            fe = powf(10000.0f, -(float)(2 * (d & 31)) / 64.0f);
            fo = powf(10000.0f, -(float)(2 * ((d + 1) & 31)) / 64.0f);
        }
        #pragma unroll
        for (int mt = 0; mt < 4; mt++) {
            #pragma unroll
            for (int hf = 0; hf < 2; hf++) {
                int m = m0 + wm * 64 + mt * 16 + g4 + hf * 8;
                float v0 = acc[mt][nt][hf * 2 + 0] + bi0;
                float v1 = acc[mt][nt][hf * 2 + 1] + bi1;
                if (mode == MODE_PLAIN) {
                    float2 o = {v0, v1};
                    *(float2*)&dstf[(size_t)m * Ev + n] = o;
                } else {
                    int b = m >> 11, srow = m & 2047;
                    if (mode != MODE_BHSD) {
                        float pos = (float)srow;
                        float se, ce, so, co;
                        sincos_red(pos * fe, &se, &ce);
                        sincos_red(pos * fo, &so, &co);
                        float r0 = v0 * ce - v1 * se;
                        float r1 = v1 * co + v0 * so;
                        v0 = r0; v1 = r1;
                        // fold 1/sqrt(64) AND 1/ln2 (softmax uses exp2)
                        if (mode == MODE_ROPEQ) {
                            v0 *= 0.18033688011112042f;
                            v1 *= 0.18033688011112042f;
                        }
                    }
                    uint32_t hw, lw;
                    split_pack(v0, v1, hw, lw);
                    size_t off = (((size_t)(b * Hv + h) * Sv + srow) << 6) + d;
                    *(uint32_t*)&dsthi[off] = hw;
                    *(uint32_t*)&dstlo[off] = lw;
                }
            }
        }
    }
}

__global__ __launch_bounds__(256, 2)
void gemm_qkv_kernel(const __nv_bfloat16* __restrict__ xhi,
                     const __nv_bfloat16* __restrict__ xlo,
                     const __nv_bfloat16* __restrict__ wqhi, const __nv_bfloat16* __restrict__ wqlo,
                     const __nv_bfloat16* __restrict__ wkhi, const __nv_bfloat16* __restrict__ wklo,
                     const __nv_bfloat16* __restrict__ wvhi, const __nv_bfloat16* __restrict__ wvlo,
                     const float* __restrict__ bq, const float* __restrict__ bk,
                     const float* __restrict__ bv,
                     __nv_bfloat16* __restrict__ qhi, __nv_bfloat16* __restrict__ qlo,
                     __nv_bfloat16* __restrict__ khi, __nv_bfloat16* __restrict__ klo,
                     __nv_bfloat16* __restrict__ vhi, __nv_bfloat16* __restrict__ vlo)
{
    int z = blockIdx.z;
    const __nv_bfloat16* whi = (z == 0) ? wqhi : (z == 1) ? wkhi : wvhi;
    const __nv_bfloat16* wlo = (z == 0) ? wqlo : (z == 1) ? wklo : wvlo;
    const float* bias = (z == 0) ? bq : (z == 1) ? bk : bv;
    __nv_bfloat16* dhi = (z == 0) ? qhi : (z == 1) ? khi : vhi;
    __nv_bfloat16* dlo = (z == 0) ? qlo : (z == 1) ? klo : vlo;
    int mode = (z == 0) ? MODE_ROPEQ : (z == 1) ? MODE_ROPEK : MODE_BHSD;
    gemm_core(xhi, xlo, whi, wlo, bias, nullptr, dhi, dlo, mode);
}

__global__ __launch_bounds__(256, 2)
void gemm_final_kernel(const __nv_bfloat16* __restrict__ ohi,
                       const __nv_bfloat16* __restrict__ olo,
                       const __nv_bfloat16* __restrict__ wohi,
                       const __nv_bfloat16* __restrict__ wolo,
                       const float* __restrict__ bo, float* __restrict__ out)
{
    gemm_core(ohi, olo, wohi, wolo, bo, out, nullptr, nullptr, MODE_PLAIN);
}

// ---------------------------------------------------------------------------
// Flash attention via mma.sync, bf16x3, software-pipelined S + term-major
// MMA interleave (RAW spacing 4 in S, 2 in PV). Softmax in base-2 domain.
// CTA = 64 queries (4 warps), 3 KV stages, 2 CTAs/SM.
// ---------------------------------------------------------------------------
#define PITCHB 144
#define NQ 64
#define QSMB (NQ * PITCHB)           // 9216
#define KVTILE (64 * PITCHB)         // 9216
#define KVSTG (4 * KVTILE)           // 36864
#define ATTN_SMEM (3 * KVSTG)        // 110592

__global__ __launch_bounds__(128, 2)
void attn_mma_kernel(const __nv_bfloat16* __restrict__ Qhi,
                     const __nv_bfloat16* __restrict__ Qlo,
                     const __nv_bfloat16* __restrict__ Khi,
                     const __nv_bfloat16* __restrict__ Klo,
                     const __nv_bfloat16* __restrict__ Vhi,
                     const __nv_bfloat16* __restrict__ Vlo,
                     __nv_bfloat16* __restrict__ Ohi,
                     __nv_bfloat16* __restrict__ Olo)
{
    extern __shared__ char dsm[];
    uint32_t stg = smem_to_u32(dsm);
    const int tid = threadIdx.x, wid = tid >> 5, lid = tid & 31;
    const int qt = (int)gridDim.x - 1 - (int)blockIdx.x;  // longest first
    const int bh = blockIdx.y;
    const int nkt = qt + 1;
    const size_t bhb = (size_t)bh * Sv * 64;

    auto stage_addr = [&](int s) { return stg + (uint32_t)s * KVSTG; };

    auto load_kv = [&](int kt, int s) {
        uint32_t sb = stage_addr(s);
        const __nv_bfloat16* srcs[4] = {
            Khi + bhb + (size_t)kt * 64 * 64, Klo + bhb + (size_t)kt * 64 * 64,
            Vhi + bhb + (size_t)kt * 64 * 64, Vlo + bhb + (size_t)kt * 64 * 64 };
        #pragma unroll
        for (int it = 0; it < 16; it++) {
            int e = it * 128 + tid;
            int tl = e >> 9, r = (e >> 3) & 63, ch = e & 7;
            CP_ASYNC16(sb + tl * KVTILE + r * PITCHB + ch * 16,
                       srcs[tl] + r * 64 + ch * 8);
        }
    };

    // ---- prologue: Q -> stage2 region (temp), KV(0), KV(1) ----
    const uint32_t qtmp = stage_addr(2);
    {
        const __nv_bfloat16* gh = Qhi + bhb + (size_t)qt * NQ * 64;
        const __nv_bfloat16* gl = Qlo + bhb + (size_t)qt * NQ * 64;
        #pragma unroll
        for (int it = 0; it < 4; it++) {
            int e = it * 128 + tid;
            int r = e >> 3, ch = e & 7;
            CP_ASYNC16(qtmp + r * PITCHB + ch * 16, gh + r * 64 + ch * 8);
            CP_ASYNC16(qtmp + QSMB + r * PITCHB + ch * 16, gl + r * 64 + ch * 8);
        }
        load_kv(0, 0);
        CP_COMMIT();                 // G0 = Q + KV(0)
        if (nkt > 1) load_kv(1, 1);
        CP_COMMIT();                 // G1 = KV(1)
    }
    CP_WAIT1();                      // G0 done
    __syncthreads();

    // Q fragments (register resident)
    uint32_t qfh[4][4], qfl[4][4];
    {
        uint32_t qfo = (wid * 16 + (lid & 15)) * PITCHB + (lid >> 4) * 16;
        #pragma unroll
        for (int kc = 0; kc < 4; kc++) {
            ldmatrix_x4(qfh[kc], qtmp + qfo + kc * 32);
            ldmatrix_x4(qfl[kc], qtmp + QSMB + qfo + kc * 32);
        }
    }

    const uint32_t kfo = ((lid >> 4) * 8 + (lid & 7)) * PITCHB + ((lid >> 3) & 1) * 16;
    const uint32_t vfo = (lid & 15) * PITCHB + (lid >> 4) * 16;
    const int g4 = lid >> 2, t2 = lid & 3;

    // Term-major S: per kc, per pair of n0t, emit each split term across
    // 4 independent accumulators (RAW spacing 4).
    auto compute_S = [&](float (&Sd)[8][4], int stage) {
        #pragma unroll
        for (int nt = 0; nt < 8; nt++)
            #pragma unroll
            for (int i = 0; i < 4; i++) Sd[nt][i] = 0.f;
        uint32_t sb = stage_addr(stage);
        #pragma unroll
        for (int kc = 0; kc < 4; kc++) {
            #pragma unroll
            for (int pr = 0; pr < 2; pr++) {
                uint32_t kh[2][4], kl[2][4];
                #pragma unroll
                for (int j = 0; j < 2; j++) {
                    int n0t = pr * 2 + j;
                    uint32_t ka = sb + (n0t * 16) * PITCHB + kc * 32 + kfo;
                    ldmatrix_x4(kh[j], ka);
                    ldmatrix_x4(kl[j], ka + KVTILE);
                }
                #pragma unroll
                for (int j = 0; j < 2; j++) {        // term qh*kh
                    int nt = (pr * 2 + j) * 2;
                    mma16816(Sd[nt], qfh[kc], kh[j]);
                    mma16816(Sd[nt + 1], qfh[kc], kh[j] + 2);
                }
                #pragma unroll
                for (int j = 0; j < 2; j++) {        // term qh*kl
                    int nt = (pr * 2 + j) * 2;
                    mma16816(Sd[nt], qfh[kc], kl[j]);
                    mma16816(Sd[nt + 1], qfh[kc], kl[j] + 2);
                }
                #pragma unroll
                for (int j = 0; j < 2; j++) {        // term ql*kh
                    int nt = (pr * 2 + j) * 2;
                    mma16816(Sd[nt], qfl[kc], kh[j]);
                    mma16816(Sd[nt + 1], qfl[kc], kh[j] + 2);
                }
            }
        }
    };

    float SA[8][4], SB[8][4];
    compute_S(SA, 0);                // S(0) while stage1/2 loads fly

    __syncthreads();                 // Q region free -> reuse as stage2
    if (nkt > 2) load_kv(2, 2);
    CP_COMMIT();                     // G2
    CP_WAIT1();                      // G1 done (stage1 ready)
    __syncthreads();

    float m0 = -1e30f, m1 = -1e30f, l0 = 0.f, l1 = 0.f;
    float accO[8][4] = {};

    auto body = [&](float (&Scur)[8][4], float (&Snext)[8][4], int kt) {
        // ---- prefetch S for kt+1 (tensor busy during softmax below) ----
        if (kt + 1 < nkt) compute_S(Snext, (kt + 1) % 3);

        // ---- causal mask (diagonal tile only) ----
        if (kt == qt) {
            int j0g = kt * 64, q0g = qt * NQ + wid * 16;
            int colb = t2 * 2, rowb = g4;
            #pragma unroll
            for (int nt = 0; nt < 8; nt++) {
                int jb = j0g + nt * 8 + colb;
                if (jb > q0g + rowb)          Scur[nt][0] = -1e30f;
                if (jb + 1 > q0g + rowb)      Scur[nt][1] = -1e30f;
                if (jb > q0g + rowb + 8)      Scur[nt][2] = -1e30f;
                if (jb + 1 > q0g + rowb + 8)  Scur[nt][3] = -1e30f;
            }
        }

        // ---- online softmax (base-2: scores pre-scaled by 1/ln2) ----
        float mx0 = -1e30f, mx1 = -1e30f;
        #pragma unroll
        for (int nt = 0; nt < 8; nt++) {
            mx0 = fmaxf(mx0, fmaxf(Scur[nt][0], Scur[nt][1]));
            mx1 = fmaxf(mx1, fmaxf(Scur[nt][2], Scur[nt][3]));
        }
        mx0 = fmaxf(mx0, __shfl_xor_sync(0xffffffffu, mx0, 1));
        mx0 = fmaxf(mx0, __shfl_xor_sync(0xffffffffu, mx0, 2));
        mx1 = fmaxf(mx1, __shfl_xor_sync(0xffffffffu, mx1, 1));
        mx1 = fmaxf(mx1, __shfl_xor_sync(0xffffffffu, mx1, 2));
        float nm0 = fmaxf(m0, mx0), nm1 = fmaxf(m1, mx1);
        float a0 = exp2f(m0 - nm0), a1 = exp2f(m1 - nm1);
        m0 = nm0; m1 = nm1;

        float rs0 = 0.f, rs1 = 0.f;
        uint32_t phA[8], phB[8], plA[8], plB[8];
        #pragma unroll
        for (int nt = 0; nt < 8; nt++) {
            float p0 = exp2f(Scur[nt][0] - nm0), p1 = exp2f(Scur[nt][1] - nm0);
            float p2 = exp2f(Scur[nt][2] - nm1), p3 = exp2f(Scur[nt][3] - nm1);
            rs0 += p0 + p1; rs1 += p2 + p3;
            split_pack(p0, p1, phA[nt], plA[nt]);
            split_pack(p2, p3, phB[nt], plB[nt]);
        }
        rs0 += __shfl_xor_sync(0xffffffffu, rs0, 1);
        rs0 += __shfl_xor_sync(0xffffffffu, rs0, 2);
        rs1 += __shfl_xor_sync(0xffffffffu, rs1, 1);
        rs1 += __shfl_xor_sync(0xffffffffu, rs1, 2);
        l0 = l0 * a0 + rs0;
        l1 = l1 * a1 + rs1;
        #pragma unroll
        for (int dt = 0; dt < 8; dt++) {
            accO[dt][0] *= a0; accO[dt][1] *= a0;
            accO[dt][2] *= a1; accO[dt][3] *= a1;
        }

        // ---- O += P V (bf16x3), alternate-acc ordering (spacing 2) ----
        uint32_t vb = stage_addr(kt % 3) + 2 * KVTILE;
        #pragma unroll
        for (int kc = 0; kc < 4; kc++) {
            uint32_t aph[4] = {phA[2 * kc], phB[2 * kc], phA[2 * kc + 1], phB[2 * kc + 1]};
            uint32_t apl[4] = {plA[2 * kc], plB[2 * kc], plA[2 * kc + 1], plB[2 * kc + 1]};
            #pragma unroll
            for (int d0t = 0; d0t < 4; d0t++) {
                uint32_t va = vb + (kc * 16) * PITCHB + d0t * 32 + vfo;
                uint32_t vh[4], vl[4];
                ldmatrix_x4t(vh, va);
                ldmatrix_x4t(vl, va + KVTILE);
                mma16816(accO[2 * d0t],     aph, vh);
                mma16816(accO[2 * d0t + 1], aph, vh + 2);
                mma16816(accO[2 * d0t],     apl, vh);
                mma16816(accO[2 * d0t + 1], apl, vh + 2);
                mma16816(accO[2 * d0t],     aph, vl);
                mma16816(accO[2 * d0t + 1], aph, vl + 2);
            }
        }

        // ---- pipeline wind: free stage kt%3, fetch kt+3 into it ----
        __syncthreads();
        if (kt + 3 < nkt) load_kv(kt + 3, kt % 3);
        CP_COMMIT();
        CP_WAIT1();                  // completes load(kt+2), needed next iter
        __syncthreads();
    };

    for (int kt = 0; kt < nkt; kt += 2) {
        body(SA, SB, kt);
        if (kt + 1 < nkt) body(SB, SA, kt + 1);
    }

    // ---- epilogue ----
    float inv0 = 1.0f / l0, inv1 = 1.0f / l1;
    int b = bh >> 4, h = bh & 15;
    int s0 = qt * NQ + wid * 16 + g4, s1 = s0 + 8;
    size_t r0o = ((size_t)(b * Sv + s0)) * Ev + h * 64;
    size_t r1o = ((size_t)(b * Sv + s1)) * Ev + h * 64;
    #pragma unroll
    for (int dt = 0; dt < 8; dt++) {
        int d = dt * 8 + t2 * 2;
        uint32_t hw, lw;
        split_pack(accO[dt][0] * inv0, accO[dt][1] * inv0, hw, lw);
        *(uint32_t*)&Ohi[r0o + d] = hw;
        *(uint32_t*)&Olo[r0o + d] = lw;
        split_pack(accO[dt][2] * inv1, accO[dt][3] * inv1, hw, lw);
        *(uint32_t*)&Ohi[r1o + d] = hw;
        *(uint32_t*)&Olo[r1o + d] = lw;
    }
}

// ---------------------------------------------------------------------------
extern "C" void kernel_launch(void* const* d_in, const int* in_sizes, int n_in,
                              void* d_out, int out_size)
{
    const float* x  = (const float*)d_in[0];
    const float* wq = (const float*)d_in[1];
    const float* bq = (const float*)d_in[2];
    const float* wk = (const float*)d_in[3];
    const float* bk = (const float*)d_in[4];
    const float* wv = (const float*)d_in[5];
    const float* bv = (const float*)d_in[6];
    const float* wo = (const float*)d_in[7];
    const float* bo = (const float*)d_in[8];
    float* out = (float*)d_out;

    cudaFuncSetAttribute(gemm_qkv_kernel,
                         cudaFuncAttributeMaxDynamicSharedMemorySize, GEMM_SMEM);
    cudaFuncSetAttribute(gemm_final_kernel,
                         cudaFuncAttributeMaxDynamicSharedMemorySize, GEMM_SMEM);
    cudaFuncSetAttribute(attn_mma_kernel,
                         cudaFuncAttributeMaxDynamicSharedMemorySize, ATTN_SMEM);

    __nv_bfloat16 *qhi, *qlo, *khi, *klo, *vhi, *vlo;
    __nv_bfloat16 *xhi, *xlo, *ohi, *olo;
    __nv_bfloat16 *wqhi, *wqlo, *wkhi, *wklo, *wvhi, *wvlo, *wohi, *wolo;
    cudaGetSymbolAddress((void**)&qhi, g_Qhi);
    cudaGetSymbolAddress((void**)&qlo, g_Qlo);
    cudaGetSymbolAddress((void**)&khi, g_Khi);
    cudaGetSymbolAddress((void**)&klo, g_Klo);
    cudaGetSymbolAddress((void**)&vhi, g_Vhi);
    cudaGetSymbolAddress((void**)&vlo, g_Vlo);
    cudaGetSymbolAddress((void**)&xhi, g_xhi);
    cudaGetSymbolAddress((void**)&xlo, g_xlo);
    cudaGetSymbolAddress((void**)&ohi, g_ohi);
    cudaGetSymbolAddress((void**)&olo, g_olo);
    cudaGetSymbolAddress((void**)&wqhi, g_wqhi);
    cudaGetSymbolAddress((void**)&wqlo, g_wqlo);
    cudaGetSymbolAddress((void**)&wkhi, g_wkhi);
    cudaGetSymbolAddress((void**)&wklo, g_wklo);
    cudaGetSymbolAddress((void**)&wvhi, g_wvhi);
    cudaGetSymbolAddress((void**)&wvlo, g_wvlo);
    cudaGetSymbolAddress((void**)&wohi, g_wohi);
    cudaGetSymbolAddress((void**)&wolo, g_wolo);

    const int NX = Mtot * Ev;
    const int NW = Ev * Ev;
    split_bf16_kernel<<<NX / 1024, 256>>>(x, xhi, xlo);
    split4_kernel<<<dim3(NW / 1024, 4), 256>>>(
        wq, wk, wv, wo,
        wqhi, wqlo, wkhi, wklo, wvhi, wvlo, wohi, wolo);

    gemm_qkv_kernel<<<dim3(Ev / 128, Mtot / 128, 3), 256, GEMM_SMEM>>>(
        xhi, xlo, wqhi, wqlo, wkhi, wklo, wvhi, wvlo,
        bq, bk, bv, qhi, qlo, khi, klo, vhi, vlo);

    attn_mma_kernel<<<dim3(Sv / NQ, Bv * Hv), 128, ATTN_SMEM>>>(
        qhi, qlo, khi, klo, vhi, vlo, ohi, olo);

    gemm_final_kernel<<<dim3(Ev / 128, Mtot / 128), 256, GEMM_SMEM>>>(
        ohi, olo, wohi, wolo, bo, out);
}

// round 12
// speedup vs baseline: 1.4884x; 1.4445x over previous
#include <cuda_runtime.h>
#include <cuda_bf16.h>
#include <cuda_fp16.h>
#include <cstdint>
#include <math.h>

#define Bv 2
#define Sv 2048
#define Ev 1024
#define Hv 16
#define Dv 64
#define Mtot (Bv * Sv)          // 4096

enum { MODE_ROPEQ = 0, MODE_ROPEK = 1, MODE_BHSD = 2, MODE_PLAIN = 3 };

// ---------------- scratch (__device__ globals; no allocs allowed) ----------
__device__ __half g_Qhi[Bv * Hv * Sv * Dv], g_Qlo[Bv * Hv * Sv * Dv];
__device__ __half g_K[Bv * Hv * Sv * Dv];
__device__ __half g_V[Bv * Hv * Sv * Dv];
__device__ __half g_xhi[Mtot * Ev], g_xlo[Mtot * Ev];
__device__ __half g_ohi[Mtot * Ev], g_olo[Mtot * Ev];
__device__ __half g_wq[Ev * Ev], g_wk[Ev * Ev], g_wv[Ev * Ev], g_wo[Ev * Ev];

// ---------------- helpers --------------------------------------------------
__device__ __forceinline__ uint32_t smem_to_u32(const void* p) {
    uint32_t a;
    asm("{ .reg .u64 t; cvta.to.shared.u64 t, %1; cvt.u32.u64 %0, t; }"
        : "=r"(a) : "l"(p));
    return a;
}

__device__ __forceinline__ void ldmatrix_x4(uint32_t* r, uint32_t addr) {
    asm volatile("ldmatrix.sync.aligned.m8n8.x4.shared.b16 {%0,%1,%2,%3}, [%4];"
                 : "=r"(r[0]), "=r"(r[1]), "=r"(r[2]), "=r"(r[3]) : "r"(addr));
}
__device__ __forceinline__ void ldmatrix_x4t(uint32_t* r, uint32_t addr) {
    asm volatile("ldmatrix.sync.aligned.m8n8.x4.trans.shared.b16 {%0,%1,%2,%3}, [%4];"
                 : "=r"(r[0]), "=r"(r[1]), "=r"(r[2]), "=r"(r[3]) : "r"(addr));
}

// fp16 inputs, fp32 accumulate
__device__ __forceinline__ void mma16816h(float* c, const uint32_t* a,
                                          const uint32_t* b) {
    asm volatile(
        "mma.sync.aligned.m16n8k16.row.col.f32.f16.f16.f32 "
        "{%0,%1,%2,%3}, {%4,%5,%6,%7}, {%8,%9}, {%0,%1,%2,%3};"
        : "+f"(c[0]), "+f"(c[1]), "+f"(c[2]), "+f"(c[3])
        : "r"(a[0]), "r"(a[1]), "r"(a[2]), "r"(a[3]), "r"(b[0]), "r"(b[1]));
}

#define CP_ASYNC16(smem, gptr) \
    asm volatile("cp.async.cg.shared.global [%0], [%1], 16;" \
                 :: "r"(smem), "l"(gptr))
#define CP_COMMIT() asm volatile("cp.async.commit_group;" ::: "memory")
#define CP_WAIT1()  asm volatile("cp.async.wait_group 1;" ::: "memory")

// sincos accurate under --use_fast_math (Cody-Waite 2*pi reduction)
__device__ __forceinline__ void sincos_red(float ang, float* s, float* c) {
    float kf = rintf(ang * 0.15915494309189535f);
    float r = fmaf(kf, -6.2831854820251465f, ang);
    r = fmaf(kf, 1.7484555e-7f, r);
    __sincosf(r, s, c);
}

// split two fp32 into packed fp16x2 (hi) + packed fp16x2 (residual lo)
__device__ __forceinline__ void split_pack_h(float p0, float p1,
                                             uint32_t& hi, uint32_t& lo) {
    __half h0 = __float2half_rn(p0), h1 = __float2half_rn(p1);
    float r0 = p0 - __half2float(h0), r1 = p1 - __half2float(h1);
    __half2 hp; hp.x = h0; hp.y = h1;
    __half2 lp; lp.x = __float2half_rn(r0); lp.y = __float2half_rn(r1);
    hi = *(uint32_t*)&hp; lo = *(uint32_t*)&lp;
}

__device__ __forceinline__ uint32_t pack_h2(float p0, float p1) {
    __half2 hp; hp.x = __float2half_rn(p0); hp.y = __float2half_rn(p1);
    return *(uint32_t*)&hp;
}

// ---------------------------------------------------------------------------
// prep kernels: x -> fp16 hi/lo split; weights -> single fp16
// ---------------------------------------------------------------------------
__global__ __launch_bounds__(256)
void split_fp16_kernel(const float* __restrict__ src,
                       __half* __restrict__ hi, __half* __restrict__ lo)
{
    int i = (blockIdx.x * 256 + threadIdx.x) * 4;
    float4 v = *(const float4*)(src + i);
    uint32_t hA, lA, hB, lB;
    split_pack_h(v.x, v.y, hA, lA);
    split_pack_h(v.z, v.w, hB, lB);
    *(uint32_t*)&hi[i]     = hA;
    *(uint32_t*)&hi[i + 2] = hB;
    *(uint32_t*)&lo[i]     = lA;
    *(uint32_t*)&lo[i + 2] = lB;
}

__global__ __launch_bounds__(256)
void convert4_fp16_kernel(const float* __restrict__ w0, const float* __restrict__ w1,
                          const float* __restrict__ w2, const float* __restrict__ w3,
                          __half* __restrict__ f0, __half* __restrict__ f1,
                          __half* __restrict__ f2, __half* __restrict__ f3)
{
    int y = blockIdx.y;
    const float* src = (y == 0) ? w0 : (y == 1) ? w1 : (y == 2) ? w2 : w3;
    __half* dst = (y == 0) ? f0 : (y == 1) ? f1 : (y == 2) ? f2 : f3;
    int i = (blockIdx.x * 256 + threadIdx.x) * 4;
    float4 v = *(const float4*)(src + i);
    *(uint32_t*)&dst[i]     = pack_h2(v.x, v.y);
    *(uint32_t*)&dst[i + 2] = pack_h2(v.z, v.w);
}

// ---------------------------------------------------------------------------
// fp16 (x2,x1) GEMM core: C[m,n] = sum_k x[m,k]*W[n,k] + bias[n].
// A-side: xh + xl (exact to 2^-22), B-side: W rounded to fp16.
// CTA 128x128, 8 warps (2x4), warp 64x32, BK=32, 2-stage cp.async, 2 CTAs/SM.
// ---------------------------------------------------------------------------
#define GBK 32
#define GNCHUNK (Ev / GBK)               // 32
#define GT 10240                         // one 128-row tile (80B pitch)
#define GSTAGE (3 * GT)                  // 30720 (xh, xl, wh)
#define GEMM_SMEM (2 * GSTAGE + 256)     // 61696

__device__ __forceinline__
void gemm_core(const __half* __restrict__ Ahi,
               const __half* __restrict__ Alo,
               const __half* __restrict__ Wh,
               const float* __restrict__ bias,
               float* __restrict__ dstf,
               __half* __restrict__ dsthi,
               __half* __restrict__ dstlo, int mode)
{
    extern __shared__ char dsm[];
    uint32_t base = (smem_to_u32(dsm) + 127) & ~127u;

    const int tid = threadIdx.x;
    const int wid = tid >> 5, lid = tid & 31;
    const int wm = wid >> 2, wn = wid & 3;       // 2x4 warp grid
    const int m0 = blockIdx.y * 128, n0 = blockIdx.x * 128;

    const __half* srcs[3] = {
        Ahi + (size_t)m0 * Ev, Alo + (size_t)m0 * Ev, Wh + (size_t)n0 * Ev };

    auto load_chunk = [&](int c, int s) {
        const int k0 = c * GBK;
        uint32_t sb = base + s * GSTAGE;
        #pragma unroll
        for (int it = 0; it < 6; it++) {
            int e = it * 256 + tid;
            int c16 = e & 3;
            int grow = e >> 2;                  // 0..383
            int tile = grow >> 7, row = grow & 127;
            uint32_t so = sb + tile * GT + row * 80 + c16 * 16;
            const void* g = srcs[tile] + (size_t)row * Ev + k0 + c16 * 8;
            CP_ASYNC16(so, g);
        }
    };

    float acc[4][4][4] = {};

    const uint32_t aoff = (lid & 15) * 80 + (lid >> 4) * 16;
    const uint32_t boff = ((lid >> 4) * 8 + (lid & 7)) * 80 + ((lid >> 3) & 1) * 16;

    load_chunk(0, 0);
    CP_COMMIT();

    for (int c = 0; c < GNCHUNK; c++) {
        if (c + 1 < GNCHUNK) load_chunk(c + 1, (c + 1) & 1);
        CP_COMMIT();
        CP_WAIT1();
        __syncthreads();

        uint32_t sb  = base + (c & 1) * GSTAGE;
        uint32_t aHI = sb + (wm * 64) * 80;
        uint32_t aLO = aHI + GT;
        uint32_t bW  = sb + 2 * GT + (wn * 32) * 80;

        #pragma unroll
        for (int ks = 0; ks < 2; ks++) {
            uint32_t kb = ks * 32;
            // W fragments (4 nt)
            uint32_t bh[4][2];
            #pragma unroll
            for (int pr = 0; pr < 2; pr++) {
                uint32_t t4[4];
                ldmatrix_x4(t4, bW + pr * (16 * 80) + kb + boff);
                bh[2 * pr][0] = t4[0]; bh[2 * pr][1] = t4[1];
                bh[2 * pr + 1][0] = t4[2]; bh[2 * pr + 1][1] = t4[3];
            }
            // term 1: ah*W
            uint32_t ah[4][4];
            #pragma unroll
            for (int mt = 0; mt < 4; mt++)
                ldmatrix_x4(ah[mt], aHI + mt * (16 * 80) + kb + aoff);
            #pragma unroll
            for (int mt = 0; mt < 4; mt++)
                #pragma unroll
                for (int nt = 0; nt < 4; nt++)
                    mma16816h(acc[mt][nt], ah[mt], bh[nt]);
            // term 2: al*W
            {
                uint32_t al[4][4];
                #pragma unroll
                for (int mt = 0; mt < 4; mt++)
                    ldmatrix_x4(al[mt], aLO + mt * (16 * 80) + kb + aoff);
                #pragma unroll
                for (int mt = 0; mt < 4; mt++)
                    #pragma unroll
                    for (int nt = 0; nt < 4; nt++)
                        mma16816h(acc[mt][nt], al[mt], bh[nt]);
            }
        }
        __syncthreads();
    }

    // ------------------- epilogue -------------------
    const int g4 = lid >> 2, t2 = lid & 3;
    #pragma unroll
    for (int nt = 0; nt < 4; nt++) {
        int n = n0 + wn * 32 + nt * 8 + t2 * 2;
        float bi0 = bias[n], bi1 = bias[n + 1];
        int h = n >> 6, d = n & 63;
        float fe = 0.f, fo = 0.f;
        if (mode == MODE_ROPEQ || mode == MODE_ROPEK) {
            fe = powf(10000.0f, -(float)(2 * (d & 31)) / 64.0f);
            fo = powf(10000.0f, -(float)(2 * ((d + 1) & 31)) / 64.0f);
        }
        #pragma unroll
        for (int mt = 0; mt < 4; mt++) {
            #pragma unroll
            for (int hf = 0; hf < 2; hf++) {
                int m = m0 + wm * 64 + mt * 16 + g4 + hf * 8;
                float v0 = acc[mt][nt][hf * 2 + 0] + bi0;
                float v1 = acc[mt][nt][hf * 2 + 1] + bi1;
                if (mode == MODE_PLAIN) {
                    float2 o = {v0, v1};
                    *(float2*)&dstf[(size_t)m * Ev + n] = o;
                } else {
                    int b = m >> 11, srow = m & 2047;
                    if (mode != MODE_BHSD) {
                        float pos = (float)srow;
                        float se, ce, so, co;
                        sincos_red(pos * fe, &se, &ce);
                        sincos_red(pos * fo, &so, &co);
                        float r0 = v0 * ce - v1 * se;
                        float r1 = v1 * co + v0 * so;
                        v0 = r0; v1 = r1;
                        // Q: fold 1/sqrt(64) AND 1/ln2 (softmax uses exp2)
                        if (mode == MODE_ROPEQ) {
                            v0 *= 0.18033688011112042f;
                            v1 *= 0.18033688011112042f;
                        }
                    }
                    size_t off = (((size_t)(b * Hv + h) * Sv + srow) << 6) + d;
                    if (mode == MODE_ROPEQ) {
                        uint32_t hw, lw;
                        split_pack_h(v0, v1, hw, lw);
                        *(uint32_t*)&dsthi[off] = hw;
                        *(uint32_t*)&dstlo[off] = lw;
                    } else {                       // K / V: single fp16
                        *(uint32_t*)&dsthi[off] = pack_h2(v0, v1);
                    }
                }
            }
        }
    }
}

__global__ __launch_bounds__(256, 2)
void gemm_qkv_kernel(const __half* __restrict__ xhi, const __half* __restrict__ xlo,
                     const __half* __restrict__ wq, const __half* __restrict__ wk,
                     const __half* __restrict__ wv,
                     const float* __restrict__ bq, const float* __restrict__ bk,
                     const float* __restrict__ bv,
                     __half* __restrict__ qhi, __half* __restrict__ qlo,
                     __half* __restrict__ kk, __half* __restrict__ vv)
{
    int z = blockIdx.z;
    const __half* w = (z == 0) ? wq : (z == 1) ? wk : wv;
    const float* bias = (z == 0) ? bq : (z == 1) ? bk : bv;
    __half* dhi = (z == 0) ? qhi : (z == 1) ? kk : vv;
    __half* dlo = (z == 0) ? qlo : nullptr;
    int mode = (z == 0) ? MODE_ROPEQ : (z == 1) ? MODE_ROPEK : MODE_BHSD;
    gemm_core(xhi, xlo, w, bias, nullptr, dhi, dlo, mode);
}

__global__ __launch_bounds__(256, 2)
void gemm_final_kernel(const __half* __restrict__ ohi, const __half* __restrict__ olo,
                       const __half* __restrict__ wo,
                       const float* __restrict__ bo, float* __restrict__ out)
{
    gemm_core(ohi, olo, wo, bo, out, nullptr, nullptr, MODE_PLAIN);
}

// ---------------------------------------------------------------------------
// Flash attention, fp16 (x2,x1): S = (qh+ql)*K, O = (ph+pl)*V; K,V single.
// Software-pipelined S, term-major interleave, base-2 softmax.
// CTA = 64 queries (4 warps), 3 KV stages (K+V = 18.4KB each), 2 CTAs/SM.
// ---------------------------------------------------------------------------
#define PITCHB 144
#define NQ 64
#define QSMB (NQ * PITCHB)           // 9216
#define KVTILE (64 * PITCHB)         // 9216
#define KVSTG (2 * KVTILE)           // 18432 (K + V)
#define ATTN_SMEM (3 * KVSTG)        // 55296

__global__ __launch_bounds__(128, 2)
void attn_mma_kernel(const __half* __restrict__ Qhi, const __half* __restrict__ Qlo,
                     const __half* __restrict__ Kk, const __half* __restrict__ Vv,
                     __half* __restrict__ Ohi, __half* __restrict__ Olo)
{
    extern __shared__ char dsm[];
    uint32_t stg = smem_to_u32(dsm);
    const int tid = threadIdx.x, wid = tid >> 5, lid = tid & 31;
    const int qt = (int)gridDim.x - 1 - (int)blockIdx.x;  // longest first
    const int bh = blockIdx.y;
    const int nkt = qt + 1;
    const size_t bhb = (size_t)bh * Sv * 64;

    auto stage_addr = [&](int s) { return stg + (uint32_t)s * KVSTG; };

    auto load_kv = [&](int kt, int s) {
        uint32_t sb = stage_addr(s);
        const __half* srcs[2] = {
            Kk + bhb + (size_t)kt * 64 * 64, Vv + bhb + (size_t)kt * 64 * 64 };
        #pragma unroll
        for (int it = 0; it < 8; it++) {
            int e = it * 128 + tid;
            int tl = e >> 9, r = (e >> 3) & 63, ch = e & 7;
            CP_ASYNC16(sb + tl * KVTILE + r * PITCHB + ch * 16,
                       srcs[tl] + r * 64 + ch * 8);
        }
    };

    // ---- prologue: Q -> stage2 region (temp), KV(0), KV(1) ----
    const uint32_t qtmp = stage_addr(2);
    {
        const __half* gh = Qhi + bhb + (size_t)qt * NQ * 64;
        const __half* gl = Qlo + bhb + (size_t)qt * NQ * 64;
        #pragma unroll
        for (int it = 0; it < 4; it++) {
            int e = it * 128 + tid;
            int r = e >> 3, ch = e & 7;
            CP_ASYNC16(qtmp + r * PITCHB + ch * 16, gh + r * 64 + ch * 8);
            CP_ASYNC16(qtmp + QSMB + r * PITCHB + ch * 16, gl + r * 64 + ch * 8);
        }
        load_kv(0, 0);
        CP_COMMIT();                 // G0 = Q + KV(0)
        if (nkt > 1) load_kv(1, 1);
        CP_COMMIT();                 // G1 = KV(1)
    }
    CP_WAIT1();                      // G0 done
    __syncthreads();

    // Q fragments (register resident)
    uint32_t qfh[4][4], qfl[4][4];
    {
        uint32_t qfo = (wid * 16 + (lid & 15)) * PITCHB + (lid >> 4) * 16;
        #pragma unroll
        for (int kc = 0; kc < 4; kc++) {
            ldmatrix_x4(qfh[kc], qtmp + qfo + kc * 32);
            ldmatrix_x4(qfl[kc], qtmp + QSMB + qfo + kc * 32);
        }
    }

    const uint32_t kfo = ((lid >> 4) * 8 + (lid & 7)) * PITCHB + ((lid >> 3) & 1) * 16;
    const uint32_t vfo = (lid & 15) * PITCHB + (lid >> 4) * 16;
    const int g4 = lid >> 2, t2 = lid & 3;

    // Term-major S: 2 terms (qh*K, ql*K), RAW spacing 4.
    auto compute_S = [&](float (&Sd)[8][4], int stage) {
        #pragma unroll
        for (int nt = 0; nt < 8; nt++)
            #pragma unroll
            for (int i = 0; i < 4; i++) Sd[nt][i] = 0.f;
        uint32_t sb = stage_addr(stage);
        #pragma unroll
        for (int kc = 0; kc < 4; kc++) {
            #pragma unroll
            for (int pr = 0; pr < 2; pr++) {
                uint32_t kh[2][4];
                #pragma unroll
                for (int j = 0; j < 2; j++) {
                    int n0t = pr * 2 + j;
                    uint32_t ka = sb + (n0t * 16) * PITCHB + kc * 32 + kfo;
                    ldmatrix_x4(kh[j], ka);
                }
                #pragma unroll
                for (int j = 0; j < 2; j++) {        // term qh*K
                    int nt = (pr * 2 + j) * 2;
                    mma16816h(Sd[nt], qfh[kc], kh[j]);
                    mma16816h(Sd[nt + 1], qfh[kc], kh[j] + 2);
                }
                #pragma unroll
                for (int j = 0; j < 2; j++) {        // term ql*K
                    int nt = (pr * 2 + j) * 2;
                    mma16816h(Sd[nt], qfl[kc], kh[j]);
                    mma16816h(Sd[nt + 1], qfl[kc], kh[j] + 2);
                }
            }
        }
    };

    float SA[8][4], SB[8][4];
    compute_S(SA, 0);                // S(0) while stage1/2 loads fly

    __syncthreads();                 // Q region free -> reuse as stage2
    if (nkt > 2) load_kv(2, 2);
    CP_COMMIT();                     // G2
    CP_WAIT1();                      // G1 done (stage1 ready)
    __syncthreads();

    float m0 = -1e30f, m1 = -1e30f, l0 = 0.f, l1 = 0.f;
    float accO[8][4] = {};

    auto body = [&](float (&Scur)[8][4], float (&Snext)[8][4], int kt) {
        // ---- prefetch S for kt+1 (tensor busy during softmax below) ----
        if (kt + 1 < nkt) compute_S(Snext, (kt + 1) % 3);

        // ---- causal mask (diagonal tile only) ----
        if (kt == qt) {
            int j0g = kt * 64, q0g = qt * NQ + wid * 16;
            int colb = t2 * 2, rowb = g4;
            #pragma unroll
            for (int nt = 0; nt < 8; nt++) {
                int jb = j0g + nt * 8 + colb;
                if (jb > q0g + rowb)          Scur[nt][0] = -1e30f;
                if (jb + 1 > q0g + rowb)      Scur[nt][1] = -1e30f;
                if (jb > q0g + rowb + 8)      Scur[nt][2] = -1e30f;
                if (jb + 1 > q0g + rowb + 8)  Scur[nt][3] = -1e30f;
            }
        }

        // ---- online softmax (base-2: scores pre-scaled by 1/ln2) ----
        float mx0 = -1e30f, mx1 = -1e30f;
        #pragma unroll
        for (int nt = 0; nt < 8; nt++) {
            mx0 = fmaxf(mx0, fmaxf(Scur[nt][0], Scur[nt][1]));
            mx1 = fmaxf(mx1, fmaxf(Scur[nt][2], Scur[nt][3]));
        }
        mx0 = fmaxf(mx0, __shfl_xor_sync(0xffffffffu, mx0, 1));
        mx0 = fmaxf(mx0, __shfl_xor_sync(0xffffffffu, mx0, 2));
        mx1 = fmaxf(mx1, __shfl_xor_sync(0xffffffffu, mx1, 1));
        mx1 = fmaxf(mx1, __shfl_xor_sync(0xffffffffu, mx1, 2));
        float nm0 = fmaxf(m0, mx0), nm1 = fmaxf(m1, mx1);
        float a0 = exp2f(m0 - nm0), a1 = exp2f(m1 - nm1);
        m0 = nm0; m1 = nm1;

        float rs0 = 0.f, rs1 = 0.f;
        uint32_t phA[8], phB[8], plA[8], plB[8];
        #pragma unroll
        for (int nt = 0; nt < 8; nt++) {
            float p0 = exp2f(Scur[nt][0] - nm0), p1 = exp2f(Scur[nt][1] - nm0);
            float p2 = exp2f(Scur[nt][2] - nm1), p3 = exp2f(Scur[nt][3] - nm1);
            rs0 += p0 + p1; rs1 += p2 + p3;
            split_pack_h(p0, p1, phA[nt], plA[nt]);
            split_pack_h(p2, p3, phB[nt], plB[nt]);
        }
        rs0 += __shfl_xor_sync(0xffffffffu, rs0, 1);
        rs0 += __shfl_xor_sync(0xffffffffu, rs0, 2);
        rs1 += __shfl_xor_sync(0xffffffffu, rs1, 1);
        rs1 += __shfl_xor_sync(0xffffffffu, rs1, 2);
        l0 = l0 * a0 + rs0;
        l1 = l1 * a1 + rs1;
        #pragma unroll
        for (int dt = 0; dt < 8; dt++) {
            accO[dt][0] *= a0; accO[dt][1] *= a0;
            accO[dt][2] *= a1; accO[dt][3] *= a1;
        }

        // ---- O += (ph + pl) * V, alternate-acc ordering ----
        uint32_t vb = stage_addr(kt % 3) + KVTILE;
        #pragma unroll
        for (int kc = 0; kc < 4; kc++) {
            uint32_t aph[4] = {phA[2 * kc], phB[2 * kc], phA[2 * kc + 1], phB[2 * kc + 1]};
            uint32_t apl[4] = {plA[2 * kc], plB[2 * kc], plA[2 * kc + 1], plB[2 * kc + 1]};
            #pragma unroll
            for (int d0t = 0; d0t < 4; d0t++) {
                uint32_t va = vb + (kc * 16) * PITCHB + d0t * 32 + vfo;
                uint32_t vh[4];
                ldmatrix_x4t(vh, va);
                mma16816h(accO[2 * d0t],     aph, vh);
                mma16816h(accO[2 * d0t + 1], aph, vh + 2);
                mma16816h(accO[2 * d0t],     apl, vh);
                mma16816h(accO[2 * d0t + 1], apl, vh + 2);
            }
        }

        // ---- pipeline wind: free stage kt%3, fetch kt+3 into it ----
        __syncthreads();
        if (kt + 3 < nkt) load_kv(kt + 3, kt % 3);
        CP_COMMIT();
        CP_WAIT1();                  // completes load(kt+2), needed next iter
        __syncthreads();
    };

    for (int kt = 0; kt < nkt; kt += 2) {
        body(SA, SB, kt);
        if (kt + 1 < nkt) body(SB, SA, kt + 1);
    }

    // ---- epilogue: normalize, fp16 split, write [M, E] ----
    float inv0 = 1.0f / l0, inv1 = 1.0f / l1;
    int b = bh >> 4, h = bh & 15;
    int s0 = qt * NQ + wid * 16 + g4, s1 = s0 + 8;
    size_t r0o = ((size_t)(b * Sv + s0)) * Ev + h * 64;
    size_t r1o = ((size_t)(b * Sv + s1)) * Ev + h * 64;
    #pragma unroll
    for (int dt = 0; dt < 8; dt++) {
        int d = dt * 8 + t2 * 2;
        uint32_t hw, lw;
        split_pack_h(accO[dt][0] * inv0, accO[dt][1] * inv0, hw, lw);
        *(uint32_t*)&Ohi[r0o + d] = hw;
        *(uint32_t*)&Olo[r0o + d] = lw;
        split_pack_h(accO[dt][2] * inv1, accO[dt][3] * inv1, hw, lw);
        *(uint32_t*)&Ohi[r1o + d] = hw;
        *(uint32_t*)&Olo[r1o + d] = lw;
    }
}

// ---------------------------------------------------------------------------
extern "C" void kernel_launch(void* const* d_in, const int* in_sizes, int n_in,
                              void* d_out, int out_size)
{
    const float* x  = (const float*)d_in[0];
    const float* wq = (const float*)d_in[1];
    const float* bq = (const float*)d_in[2];
    const float* wk = (const float*)d_in[3];
    const float* bk = (const float*)d_in[4];
    const float* wv = (const float*)d_in[5];
    const float* bv = (const float*)d_in[6];
    const float* wo = (const float*)d_in[7];
    const float* bo = (const float*)d_in[8];
    float* out = (float*)d_out;

    cudaFuncSetAttribute(gemm_qkv_kernel,
                         cudaFuncAttributeMaxDynamicSharedMemorySize, GEMM_SMEM);
    cudaFuncSetAttribute(gemm_final_kernel,
                         cudaFuncAttributeMaxDynamicSharedMemorySize, GEMM_SMEM);
    cudaFuncSetAttribute(attn_mma_kernel,
                         cudaFuncAttributeMaxDynamicSharedMemorySize, ATTN_SMEM);

    __half *qhi, *qlo, *kk, *vv, *xhi, *xlo, *ohi, *olo;
    __half *wqh, *wkh, *wvh, *woh;
    cudaGetSymbolAddress((void**)&qhi, g_Qhi);
    cudaGetSymbolAddress((void**)&qlo, g_Qlo);
    cudaGetSymbolAddress((void**)&kk, g_K);
    cudaGetSymbolAddress((void**)&vv, g_V);
    cudaGetSymbolAddress((void**)&xhi, g_xhi);
    cudaGetSymbolAddress((void**)&xlo, g_xlo);
    cudaGetSymbolAddress((void**)&ohi, g_ohi);
    cudaGetSymbolAddress((void**)&olo, g_olo);
    cudaGetSymbolAddress((void**)&wqh, g_wq);
    cudaGetSymbolAddress((void**)&wkh, g_wk);
    cudaGetSymbolAddress((void**)&wvh, g_wv);
    cudaGetSymbolAddress((void**)&woh, g_wo);

    const int NX = Mtot * Ev;
    const int NW = Ev * Ev;
    split_fp16_kernel<<<NX / 1024, 256>>>(x, xhi, xlo);
    convert4_fp16_kernel<<<dim3(NW / 1024, 4), 256>>>(
        wq, wk, wv, wo, wqh, wkh, wvh, woh);

    gemm_qkv_kernel<<<dim3(Ev / 128, Mtot / 128, 3), 256, GEMM_SMEM>>>(
        xhi, xlo, wqh, wkh, wvh, bq, bk, bv, qhi, qlo, kk, vv);

    attn_mma_kernel<<<dim3(Sv / NQ, Bv * Hv), 128, ATTN_SMEM>>>(
        qhi, qlo, kk, vv, ohi, olo);

    gemm_final_kernel<<<dim3(Ev / 128, Mtot / 128), 256, GEMM_SMEM>>>(
        ohi, olo, woh, bo, out);
}

// round 14
// speedup vs baseline: 1.7800x; 1.1959x over previous
#include <cuda_runtime.h>
#include <cuda_bf16.h>
#include <cuda_fp16.h>
#include <cstdint>
#include <math.h>

#define Bv 2
#define Sv 2048
#define Ev 1024
#define Hv 16
#define Dv 64
#define Mtot (Bv * Sv)          // 4096

enum { MODE_ROPEQ = 0, MODE_ROPEK = 1, MODE_BHSD = 2, MODE_PLAIN = 3 };

// ---------------- scratch (__device__ globals; no allocs allowed) ----------
__device__ __half g_Qhi[Bv * Hv * Sv * Dv], g_Qlo[Bv * Hv * Sv * Dv];
__device__ __half g_K[Bv * Hv * Sv * Dv];
__device__ __half g_V[Bv * Hv * Sv * Dv];
__device__ __half g_xhi[Mtot * Ev], g_xlo[Mtot * Ev];
__device__ __half g_ohi[Mtot * Ev], g_olo[Mtot * Ev];
__device__ __half g_wq[Ev * Ev], g_wk[Ev * Ev], g_wv[Ev * Ev], g_wo[Ev * Ev];

// ---------------- helpers --------------------------------------------------
__device__ __forceinline__ uint32_t smem_to_u32(const void* p) {
    uint32_t a;
    asm("{ .reg .u64 t; cvta.to.shared.u64 t, %1; cvt.u32.u64 %0, t; }"
        : "=r"(a) : "l"(p));
    return a;
}

__device__ __forceinline__ void ldmatrix_x4(uint32_t* r, uint32_t addr) {
    asm volatile("ldmatrix.sync.aligned.m8n8.x4.shared.b16 {%0,%1,%2,%3}, [%4];"
                 : "=r"(r[0]), "=r"(r[1]), "=r"(r[2]), "=r"(r[3]) : "r"(addr));
}
__device__ __forceinline__ void ldmatrix_x4t(uint32_t* r, uint32_t addr) {
    asm volatile("ldmatrix.sync.aligned.m8n8.x4.trans.shared.b16 {%0,%1,%2,%3}, [%4];"
                 : "=r"(r[0]), "=r"(r[1]), "=r"(r[2]), "=r"(r[3]) : "r"(addr));
}

// fp16 inputs, fp32 accumulate
__device__ __forceinline__ void mma16816h(float* c, const uint32_t* a,
                                          const uint32_t* b) {
    asm volatile(
        "mma.sync.aligned.m16n8k16.row.col.f32.f16.f16.f32 "
        "{%0,%1,%2,%3}, {%4,%5,%6,%7}, {%8,%9}, {%0,%1,%2,%3};"
        : "+f"(c[0]), "+f"(c[1]), "+f"(c[2]), "+f"(c[3])
        : "r"(a[0]), "r"(a[1]), "r"(a[2]), "r"(a[3]), "r"(b[0]), "r"(b[1]));
}

#define CP_ASYNC16(smem, gptr) \
    asm volatile("cp.async.cg.shared.global [%0], [%1], 16;" \
                 :: "r"(smem), "l"(gptr))
#define CP_COMMIT() asm volatile("cp.async.commit_group;" ::: "memory")
#define CP_WAIT1()  asm volatile("cp.async.wait_group 1;" ::: "memory")

// sincos accurate under --use_fast_math (Cody-Waite 2*pi reduction)
__device__ __forceinline__ void sincos_red(float ang, float* s, float* c) {
    float kf = rintf(ang * 0.15915494309189535f);
    float r = fmaf(kf, -6.2831854820251465f, ang);
    r = fmaf(kf, 1.7484555e-7f, r);
    __sincosf(r, s, c);
}

// split two fp32 into packed fp16x2 (hi) + packed fp16x2 (residual lo)
__device__ __forceinline__ void split_pack_h(float p0, float p1,
                                             uint32_t& hi, uint32_t& lo) {
    __half h0 = __float2half_rn(p0), h1 = __float2half_rn(p1);
    float r0 = p0 - __half2float(h0), r1 = p1 - __half2float(h1);
    __half2 hp; hp.x = h0; hp.y = h1;
    __half2 lp; lp.x = __float2half_rn(r0); lp.y = __float2half_rn(r1);
    hi = *(uint32_t*)&hp; lo = *(uint32_t*)&lp;
}

__device__ __forceinline__ uint32_t pack_h2(float p0, float p1) {
    __half2 hp; hp.x = __float2half_rn(p0); hp.y = __float2half_rn(p1);
    return *(uint32_t*)&hp;
}

// ---------------------------------------------------------------------------
// prep kernels: x -> fp16 hi/lo split; weights -> single fp16
// ---------------------------------------------------------------------------
__global__ __launch_bounds__(256)
void split_fp16_kernel(const float* __restrict__ src,
                       __half* __restrict__ hi, __half* __restrict__ lo)
{
    int i = (blockIdx.x * 256 + threadIdx.x) * 4;
    float4 v = *(const float4*)(src + i);
    uint32_t hA, lA, hB, lB;
    split_pack_h(v.x, v.y, hA, lA);
    split_pack_h(v.z, v.w, hB, lB);
    *(uint32_t*)&hi[i]     = hA;
    *(uint32_t*)&hi[i + 2] = hB;
    *(uint32_t*)&lo[i]     = lA;
    *(uint32_t*)&lo[i + 2] = lB;
}

__global__ __launch_bounds__(256)
void convert4_fp16_kernel(const float* __restrict__ w0, const float* __restrict__ w1,
                          const float* __restrict__ w2, const float* __restrict__ w3,
                          __half* __restrict__ f0, __half* __restrict__ f1,
                          __half* __restrict__ f2, __half* __restrict__ f3)
{
    int y = blockIdx.y;
    const float* src = (y == 0) ? w0 : (y == 1) ? w1 : (y == 2) ? w2 : w3;
    __half* dst = (y == 0) ? f0 : (y == 1) ? f1 : (y == 2) ? f2 : f3;
    int i = (blockIdx.x * 256 + threadIdx.x) * 4;
    float4 v = *(const float4*)(src + i);
    *(uint32_t*)&dst[i]     = pack_h2(v.x, v.y);
    *(uint32_t*)&dst[i + 2] = pack_h2(v.z, v.w);
}

// ---------------------------------------------------------------------------
// fp16 GEMM core: C[m,n] = sum_k x[m,k]*W[n,k] + bias[n].
// 2-term (xh+xl) only for Q-projection and the final GEMM (outputs that must
// be better than fp16); 1-term for K/V projections (outputs are rounded to
// fp16 anyway). CTA 128x128, 8 warps, warp 64x32, BK=32, 2 CTAs/SM.
// ---------------------------------------------------------------------------
#define GBK 32
#define GNCHUNK (Ev / GBK)               // 32
#define GT 10240                         // one 128-row tile (80B pitch)
#define GSTAGE (3 * GT)                  // 30720 (xh, xl, wh)
#define GEMM_SMEM (2 * GSTAGE + 256)     // 61696

__device__ __forceinline__
void gemm_core(const __half* __restrict__ Ahi,
               const __half* __restrict__ Alo,
               const __half* __restrict__ Wh,
               const float* __restrict__ bias,
               float* __restrict__ dstf,
               __half* __restrict__ dsthi,
               __half* __restrict__ dstlo, int mode)
{
    extern __shared__ char dsm[];
    uint32_t base = (smem_to_u32(dsm) + 127) & ~127u;

    const bool two_term = (mode == MODE_ROPEQ || mode == MODE_PLAIN);
    const int tid = threadIdx.x;
    const int wid = tid >> 5, lid = tid & 31;
    const int wm = wid >> 2, wn = wid & 3;       // 2x4 warp grid
    const int m0 = blockIdx.y * 128, n0 = blockIdx.x * 128;

    const __half* srcs[3] = {
        Ahi + (size_t)m0 * Ev, Alo + (size_t)m0 * Ev, Wh + (size_t)n0 * Ev };

    auto load_chunk = [&](int c, int s) {
        const int k0 = c * GBK;
        uint32_t sb = base + s * GSTAGE;
        #pragma unroll
        for (int it = 0; it < 6; it++) {
            int e = it * 256 + tid;
            int c16 = e & 3;
            int grow = e >> 2;                  // 0..383
            int tile = grow >> 7, row = grow & 127;
            uint32_t so = sb + tile * GT + row * 80 + c16 * 16;
            const void* g = srcs[tile] + (size_t)row * Ev + k0 + c16 * 8;
            CP_ASYNC16(so, g);
        }
    };

    float acc[4][4][4] = {};

    const uint32_t aoff = (lid & 15) * 80 + (lid >> 4) * 16;
    const uint32_t boff = ((lid >> 4) * 8 + (lid & 7)) * 80 + ((lid >> 3) & 1) * 16;

    load_chunk(0, 0);
    CP_COMMIT();

    for (int c = 0; c < GNCHUNK; c++) {
        if (c + 1 < GNCHUNK) load_chunk(c + 1, (c + 1) & 1);
        CP_COMMIT();
        CP_WAIT1();
        __syncthreads();

        uint32_t sb  = base + (c & 1) * GSTAGE;
        uint32_t aHI = sb + (wm * 64) * 80;
        uint32_t aLO = aHI + GT;
        uint32_t bW  = sb + 2 * GT + (wn * 32) * 80;

        #pragma unroll
        for (int ks = 0; ks < 2; ks++) {
            uint32_t kb = ks * 32;
            // W fragments (4 nt)
            uint32_t bh[4][2];
            #pragma unroll
            for (int pr = 0; pr < 2; pr++) {
                uint32_t t4[4];
                ldmatrix_x4(t4, bW + pr * (16 * 80) + kb + boff);
                bh[2 * pr][0] = t4[0]; bh[2 * pr][1] = t4[1];
                bh[2 * pr + 1][0] = t4[2]; bh[2 * pr + 1][1] = t4[3];
            }
            // term 1: ah*W
            uint32_t ah[4][4];
            #pragma unroll
            for (int mt = 0; mt < 4; mt++)
                ldmatrix_x4(ah[mt], aHI + mt * (16 * 80) + kb + aoff);
            #pragma unroll
            for (int mt = 0; mt < 4; mt++)
                #pragma unroll
                for (int nt = 0; nt < 4; nt++)
                    mma16816h(acc[mt][nt], ah[mt], bh[nt]);
            // term 2: al*W (Q-projection and final GEMM only)
            if (two_term) {
                uint32_t al[4][4];
                #pragma unroll
                for (int mt = 0; mt < 4; mt++)
                    ldmatrix_x4(al[mt], aLO + mt * (16 * 80) + kb + aoff);
                #pragma unroll
                for (int mt = 0; mt < 4; mt++)
                    #pragma unroll
                    for (int nt = 0; nt < 4; nt++)
                        mma16816h(acc[mt][nt], al[mt], bh[nt]);
            }
        }
        __syncthreads();
    }

    // ------------------- epilogue -------------------
    const int g4 = lid >> 2, t2 = lid & 3;
    #pragma unroll
    for (int nt = 0; nt < 4; nt++) {
        int n = n0 + wn * 32 + nt * 8 + t2 * 2;
        float bi0 = bias[n], bi1 = bias[n + 1];
        int h = n >> 6, d = n & 63;
        float fe = 0.f, fo = 0.f;
        if (mode == MODE_ROPEQ || mode == MODE_ROPEK) {
            fe = powf(10000.0f, -(float)(2 * (d & 31)) / 64.0f);
            fo = powf(10000.0f, -(float)(2 * ((d + 1) & 31)) / 64.0f);
        }
        #pragma unroll
        for (int mt = 0; mt < 4; mt++) {
            #pragma unroll
            for (int hf = 0; hf < 2; hf++) {
                int m = m0 + wm * 64 + mt * 16 + g4 + hf * 8;
                float v0 = acc[mt][nt][hf * 2 + 0] + bi0;
                float v1 = acc[mt][nt][hf * 2 + 1] + bi1;
                if (mode == MODE_PLAIN) {
                    float2 o = {v0, v1};
                    *(float2*)&dstf[(size_t)m * Ev + n] = o;
                } else {
                    int b = m >> 11, srow = m & 2047;
                    if (mode != MODE_BHSD) {
                        float pos = (float)srow;
                        float se, ce, so, co;
                        sincos_red(pos * fe, &se, &ce);
                        sincos_red(pos * fo, &so, &co);
                        float r0 = v0 * ce - v1 * se;
                        float r1 = v1 * co + v0 * so;
                        v0 = r0; v1 = r1;
                        // Q: fold 1/sqrt(64) AND 1/ln2 (softmax uses exp2)
                        if (mode == MODE_ROPEQ) {
                            v0 *= 0.18033688011112042f;
                            v1 *= 0.18033688011112042f;
                        }
                    }
                    size_t off = (((size_t)(b * Hv + h) * Sv + srow) << 6) + d;
                    if (mode == MODE_ROPEQ) {
                        uint32_t hw, lw;
                        split_pack_h(v0, v1, hw, lw);
                        *(uint32_t*)&dsthi[off] = hw;
                        *(uint32_t*)&dstlo[off] = lw;
                    } else {                       // K / V: single fp16
                        *(uint32_t*)&dsthi[off] = pack_h2(v0, v1);
                    }
                }
            }
        }
    }
}

__global__ __launch_bounds__(256, 2)
void gemm_qkv_kernel(const __half* __restrict__ xhi, const __half* __restrict__ xlo,
                     const __half* __restrict__ wq, const __half* __restrict__ wk,
                     const __half* __restrict__ wv,
                     const float* __restrict__ bq, const float* __restrict__ bk,
                     const float* __restrict__ bv,
                     __half* __restrict__ qhi, __half* __restrict__ qlo,
                     __half* __restrict__ kk, __half* __restrict__ vv)
{
    int z = blockIdx.z;
    const __half* w = (z == 0) ? wq : (z == 1) ? wk : wv;
    const float* bias = (z == 0) ? bq : (z == 1) ? bk : bv;
    __half* dhi = (z == 0) ? qhi : (z == 1) ? kk : vv;
    __half* dlo = (z == 0) ? qlo : nullptr;
    int mode = (z == 0) ? MODE_ROPEQ : (z == 1) ? MODE_ROPEK : MODE_BHSD;
    gemm_core(xhi, xlo, w, bias, nullptr, dhi, dlo, mode);
}

__global__ __launch_bounds__(256, 2)
void gemm_final_kernel(const __half* __restrict__ ohi, const __half* __restrict__ olo,
                       const __half* __restrict__ wo,
                       const float* __restrict__ bo, float* __restrict__ out)
{
    gemm_core(ohi, olo, wo, bo, out, nullptr, nullptr, MODE_PLAIN);
}

// ---------------------------------------------------------------------------
// Flash attention, fp16: S = (qh+ql)*K (2-term), O = ph*V (1-term).
// Software-pipelined S, term-major interleave, base-2 softmax.
// CTA = 64 queries (4 warps), 3 KV stages, 2 CTAs/SM.
// ---------------------------------------------------------------------------
#define PITCHB 144
#define NQ 64
#define QSMB (NQ * PITCHB)           // 9216
#define KVTILE (64 * PITCHB)         // 9216
#define KVSTG (2 * KVTILE)           // 18432 (K + V)
#define ATTN_SMEM (3 * KVSTG)        // 55296

__global__ __launch_bounds__(128, 2)
void attn_mma_kernel(const __half* __restrict__ Qhi, const __half* __restrict__ Qlo,
                     const __half* __restrict__ Kk, const __half* __restrict__ Vv,
                     __half* __restrict__ Ohi, __half* __restrict__ Olo)
{
    extern __shared__ char dsm[];
    uint32_t stg = smem_to_u32(dsm);
    const int tid = threadIdx.x, wid = tid >> 5, lid = tid & 31;
    const int qt = (int)gridDim.x - 1 - (int)blockIdx.x;  // longest first
    const int bh = blockIdx.y;
    const int nkt = qt + 1;
    const size_t bhb = (size_t)bh * Sv * 64;

    auto stage_addr = [&](int s) { return stg + (uint32_t)s * KVSTG; };

    auto load_kv = [&](int kt, int s) {
        uint32_t sb = stage_addr(s);
        const __half* srcs[2] = {
            Kk + bhb + (size_t)kt * 64 * 64, Vv + bhb + (size_t)kt * 64 * 64 };
        #pragma unroll
        for (int it = 0; it < 8; it++) {
            int e = it * 128 + tid;
            int tl = e >> 9, r = (e >> 3) & 63, ch = e & 7;
            CP_ASYNC16(sb + tl * KVTILE + r * PITCHB + ch * 16,
                       srcs[tl] + r * 64 + ch * 8);
        }
    };

    // ---- prologue: Q -> stage2 region (temp), KV(0), KV(1) ----
    const uint32_t qtmp = stage_addr(2);
    {
        const __half* gh = Qhi + bhb + (size_t)qt * NQ * 64;
        const __half* gl = Qlo + bhb + (size_t)qt * NQ * 64;
        #pragma unroll
        for (int it = 0; it < 4; it++) {
            int e = it * 128 + tid;
            int r = e >> 3, ch = e & 7;
            CP_ASYNC16(qtmp + r * PITCHB + ch * 16, gh + r * 64 + ch * 8);
            CP_ASYNC16(qtmp + QSMB + r * PITCHB + ch * 16, gl + r * 64 + ch * 8);
        }
        load_kv(0, 0);
        CP_COMMIT();                 // G0 = Q + KV(0)
        if (nkt > 1) load_kv(1, 1);
        CP_COMMIT();                 // G1 = KV(1)
    }
    CP_WAIT1();                      // G0 done
    __syncthreads();

    // Q fragments (register resident)
    uint32_t qfh[4][4], qfl[4][4];
    {
        uint32_t qfo = (wid * 16 + (lid & 15)) * PITCHB + (lid >> 4) * 16;
        #pragma unroll
        for (int kc = 0; kc < 4; kc++) {
            ldmatrix_x4(qfh[kc], qtmp + qfo + kc * 32);
            ldmatrix_x4(qfl[kc], qtmp + QSMB + qfo + kc * 32);
        }
    }

    const uint32_t kfo = ((lid >> 4) * 8 + (lid & 7)) * PITCHB + ((lid >> 3) & 1) * 16;
    const uint32_t vfo = (lid & 15) * PITCHB + (lid >> 4) * 16;
    const int g4 = lid >> 2, t2 = lid & 3;

    // Term-major S: 2 terms (qh*K, ql*K), RAW spacing 4.
    auto compute_S = [&](float (&Sd)[8][4], int stage) {
        #pragma unroll
        for (int nt = 0; nt < 8; nt++)
            #pragma unroll
            for (int i = 0; i < 4; i++) Sd[nt][i] = 0.f;
        uint32_t sb = stage_addr(stage);
        #pragma unroll
        for (int kc = 0; kc < 4; kc++) {
            #pragma unroll
            for (int pr = 0; pr < 2; pr++) {
                uint32_t kh[2][4];
                #pragma unroll
                for (int j = 0; j < 2; j++) {
                    int n0t = pr * 2 + j;
                    uint32_t ka = sb + (n0t * 16) * PITCHB + kc * 32 + kfo;
                    ldmatrix_x4(kh[j], ka);
                }
                #pragma unroll
                for (int j = 0; j < 2; j++) {        // term qh*K
                    int nt = (pr * 2 + j) * 2;
                    mma16816h(Sd[nt], qfh[kc], kh[j]);
                    mma16816h(Sd[nt + 1], qfh[kc], kh[j] + 2);
                }
                #pragma unroll
                for (int j = 0; j < 2; j++) {        // term ql*K
                    int nt = (pr * 2 + j) * 2;
                    mma16816h(Sd[nt], qfl[kc], kh[j]);
                    mma16816h(Sd[nt + 1], qfl[kc], kh[j] + 2);
                }
            }
        }
    };

    float SA[8][4], SB[8][4];
    compute_S(SA, 0);                // S(0) while stage1/2 loads fly

    __syncthreads();                 // Q region free -> reuse as stage2
    if (nkt > 2) load_kv(2, 2);
    CP_COMMIT();                     // G2
    CP_WAIT1();                      // G1 done (stage1 ready)
    __syncthreads();

    float m0 = -1e30f, m1 = -1e30f, l0 = 0.f, l1 = 0.f;
    float accO[8][4] = {};

    auto body = [&](float (&Scur)[8][4], float (&Snext)[8][4], int kt) {
        // ---- prefetch S for kt+1 (tensor busy during softmax below) ----
        if (kt + 1 < nkt) compute_S(Snext, (kt + 1) % 3);

        // ---- causal mask (diagonal tile only) ----
        if (kt == qt) {
            int j0g = kt * 64, q0g = qt * NQ + wid * 16;
            int colb = t2 * 2, rowb = g4;
            #pragma unroll
            for (int nt = 0; nt < 8; nt++) {
                int jb = j0g + nt * 8 + colb;
                if (jb > q0g + rowb)          Scur[nt][0] = -1e30f;
                if (jb + 1 > q0g + rowb)      Scur[nt][1] = -1e30f;
                if (jb > q0g + rowb + 8)      Scur[nt][2] = -1e30f;
                if (jb + 1 > q0g + rowb + 8)  Scur[nt][3] = -1e30f;
            }
        }

        // ---- online softmax (base-2: scores pre-scaled by 1/ln2) ----
        float mx0 = -1e30f, mx1 = -1e30f;
        #pragma unroll
        for (int nt = 0; nt < 8; nt++) {
            mx0 = fmaxf(mx0, fmaxf(Scur[nt][0], Scur[nt][1]));
            mx1 = fmaxf(mx1, fmaxf(Scur[nt][2], Scur[nt][3]));
        }
        mx0 = fmaxf(mx0, __shfl_xor_sync(0xffffffffu, mx0, 1));
        mx0 = fmaxf(mx0, __shfl_xor_sync(0xffffffffu, mx0, 2));
        mx1 = fmaxf(mx1, __shfl_xor_sync(0xffffffffu, mx1, 1));
        mx1 = fmaxf(mx1, __shfl_xor_sync(0xffffffffu, mx1, 2));
        float nm0 = fmaxf(m0, mx0), nm1 = fmaxf(m1, mx1);
        float a0 = exp2f(m0 - nm0), a1 = exp2f(m1 - nm1);
        m0 = nm0; m1 = nm1;

        float rs0 = 0.f, rs1 = 0.f;
        uint32_t phA[8], phB[8];
        #pragma unroll
        for (int nt = 0; nt < 8; nt++) {
            float p0 = exp2f(Scur[nt][0] - nm0), p1 = exp2f(Scur[nt][1] - nm0);
            float p2 = exp2f(Scur[nt][2] - nm1), p3 = exp2f(Scur[nt][3] - nm1);
            rs0 += p0 + p1; rs1 += p2 + p3;
            phA[nt] = pack_h2(p0, p1);
            phB[nt] = pack_h2(p2, p3);
        }
        rs0 += __shfl_xor_sync(0xffffffffu, rs0, 1);
        rs0 += __shfl_xor_sync(0xffffffffu, rs0, 2);
        rs1 += __shfl_xor_sync(0xffffffffu, rs1, 1);
        rs1 += __shfl_xor_sync(0xffffffffu, rs1, 2);
        l0 = l0 * a0 + rs0;
        l1 = l1 * a1 + rs1;
        #pragma unroll
        for (int dt = 0; dt < 8; dt++) {
            accO[dt][0] *= a0; accO[dt][1] *= a0;
            accO[dt][2] *= a1; accO[dt][3] *= a1;
        }

        // ---- O += ph * V (single term), alternate-acc ordering ----
        uint32_t vb = stage_addr(kt % 3) + KVTILE;
        #pragma unroll
        for (int kc = 0; kc < 4; kc++) {
            uint32_t aph[4] = {phA[2 * kc], phB[2 * kc], phA[2 * kc + 1], phB[2 * kc + 1]};
            #pragma unroll
            for (int d0t = 0; d0t < 4; d0t++) {
                uint32_t va = vb + (kc * 16) * PITCHB + d0t * 32 + vfo;
                uint32_t vh[4];
                ldmatrix_x4t(vh, va);
                mma16816h(accO[2 * d0t],     aph, vh);
                mma16816h(accO[2 * d0t + 1], aph, vh + 2);
            }
        }

        // ---- pipeline wind: free stage kt%3, fetch kt+3 into it ----
        __syncthreads();
        if (kt + 3 < nkt) load_kv(kt + 3, kt % 3);
        CP_COMMIT();
        CP_WAIT1();                  // completes load(kt+2), needed next iter
        __syncthreads();
    };

    for (int kt = 0; kt < nkt; kt += 2) {
        body(SA, SB, kt);
        if (kt + 1 < nkt) body(SB, SA, kt + 1);
    }

    // ---- epilogue: normalize, fp16 split, write [M, E] ----
    float inv0 = 1.0f / l0, inv1 = 1.0f / l1;
    int b = bh >> 4, h = bh & 15;
    int s0 = qt * NQ + wid * 16 + g4, s1 = s0 + 8;
    size_t r0o = ((size_t)(b * Sv + s0)) * Ev + h * 64;
    size_t r1o = ((size_t)(b * Sv + s1)) * Ev + h * 64;
    #pragma unroll
    for (int dt = 0; dt < 8; dt++) {
        int d = dt * 8 + t2 * 2;
        uint32_t hw, lw;
        split_pack_h(accO[dt][0] * inv0, accO[dt][1] * inv0, hw, lw);
        *(uint32_t*)&Ohi[r0o + d] = hw;
        *(uint32_t*)&Olo[r0o + d] = lw;
        split_pack_h(accO[dt][2] * inv1, accO[dt][3] * inv1, hw, lw);
        *(uint32_t*)&Ohi[r1o + d] = hw;
        *(uint32_t*)&Olo[r1o + d] = lw;
    }
}

// ---------------------------------------------------------------------------
extern "C" void kernel_launch(void* const* d_in, const int* in_sizes, int n_in,
                              void* d_out, int out_size)
{
    const float* x  = (const float*)d_in[0];
    const float* wq = (const float*)d_in[1];
    const float* bq = (const float*)d_in[2];
    const float* wk = (const float*)d_in[3];
    const float* bk = (const float*)d_in[4];
    const float* wv = (const float*)d_in[5];
    const float* bv = (const float*)d_in[6];
    const float* wo = (const float*)d_in[7];
    const float* bo = (const float*)d_in[8];
    float* out = (float*)d_out;

    cudaFuncSetAttribute(gemm_qkv_kernel,
                         cudaFuncAttributeMaxDynamicSharedMemorySize, GEMM_SMEM);
    cudaFuncSetAttribute(gemm_final_kernel,
                         cudaFuncAttributeMaxDynamicSharedMemorySize, GEMM_SMEM);
    cudaFuncSetAttribute(attn_mma_kernel,
                         cudaFuncAttributeMaxDynamicSharedMemorySize, ATTN_SMEM);

    __half *qhi, *qlo, *kk, *vv, *xhi, *xlo, *ohi, *olo;
    __half *wqh, *wkh, *wvh, *woh;
    cudaGetSymbolAddress((void**)&qhi, g_Qhi);
    cudaGetSymbolAddress((void**)&qlo, g_Qlo);
    cudaGetSymbolAddress((void**)&kk, g_K);
    cudaGetSymbolAddress((void**)&vv, g_V);
    cudaGetSymbolAddress((void**)&xhi, g_xhi);
    cudaGetSymbolAddress((void**)&xlo, g_xlo);
    cudaGetSymbolAddress((void**)&ohi, g_ohi);
    cudaGetSymbolAddress((void**)&olo, g_olo);
    cudaGetSymbolAddress((void**)&wqh, g_wq);
    cudaGetSymbolAddress((void**)&wkh, g_wk);
    cudaGetSymbolAddress((void**)&wvh, g_wv);
    cudaGetSymbolAddress((void**)&woh, g_wo);

    const int NX = Mtot * Ev;
    const int NW = Ev * Ev;
    split_fp16_kernel<<<NX / 1024, 256>>>(x, xhi, xlo);
    convert4_fp16_kernel<<<dim3(NW / 1024, 4), 256>>>(
        wq, wk, wv, wo, wqh, wkh, wvh, woh);

    gemm_qkv_kernel<<<dim3(Ev / 128, Mtot / 128, 3), 256, GEMM_SMEM>>>(
        xhi, xlo, wqh, wkh, wvh, bq, bk, bv, qhi, qlo, kk, vv);

    attn_mma_kernel<<<dim3(Sv / NQ, Bv * Hv), 128, ATTN_SMEM>>>(
        qhi, qlo, kk, vv, ohi, olo);

    gemm_final_kernel<<<dim3(Ev / 128, Mtot / 128), 256, GEMM_SMEM>>>(
        ohi, olo, woh, bo, out);
}

// round 16
// speedup vs baseline: 2.4016x; 1.3492x over previous
#include <cuda_runtime.h>
#include <cuda_bf16.h>
#include <cuda_fp16.h>
#include <cstdint>
#include <math.h>

#define Bv 2
#define Sv 2048
#define Ev 1024
#define Hv 16
#define Dv 64
#define Mtot (Bv * Sv)          // 4096

enum { MODE_ROPEQ = 0, MODE_ROPEK = 1, MODE_BHSD = 2, MODE_PLAIN = 3 };

// ---------------- scratch (__device__ globals; no allocs allowed) ----------
__device__ __half g_Q[Bv * Hv * Sv * Dv];
__device__ __half g_K[Bv * Hv * Sv * Dv];
__device__ __half g_V[Bv * Hv * Sv * Dv];
__device__ __half g_x[Mtot * Ev];
__device__ __half g_O[Mtot * Ev];
__device__ __half g_wq[Ev * Ev], g_wk[Ev * Ev], g_wv[Ev * Ev], g_wo[Ev * Ev];

// ---------------- helpers --------------------------------------------------
__device__ __forceinline__ uint32_t smem_to_u32(const void* p) {
    uint32_t a;
    asm("{ .reg .u64 t; cvta.to.shared.u64 t, %1; cvt.u32.u64 %0, t; }"
        : "=r"(a) : "l"(p));
    return a;
}

__device__ __forceinline__ void ldmatrix_x4(uint32_t* r, uint32_t addr) {
    asm volatile("ldmatrix.sync.aligned.m8n8.x4.shared.b16 {%0,%1,%2,%3}, [%4];"
                 : "=r"(r[0]), "=r"(r[1]), "=r"(r[2]), "=r"(r[3]) : "r"(addr));
}
__device__ __forceinline__ void ldmatrix_x4t(uint32_t* r, uint32_t addr) {
    asm volatile("ldmatrix.sync.aligned.m8n8.x4.trans.shared.b16 {%0,%1,%2,%3}, [%4];"
                 : "=r"(r[0]), "=r"(r[1]), "=r"(r[2]), "=r"(r[3]) : "r"(addr));
}

// fp16 inputs, fp32 accumulate
__device__ __forceinline__ void mma16816h(float* c, const uint32_t* a,
                                          const uint32_t* b) {
    asm volatile(
        "mma.sync.aligned.m16n8k16.row.col.f32.f16.f16.f32 "
        "{%0,%1,%2,%3}, {%4,%5,%6,%7}, {%8,%9}, {%0,%1,%2,%3};"
        : "+f"(c[0]), "+f"(c[1]), "+f"(c[2]), "+f"(c[3])
        : "r"(a[0]), "r"(a[1]), "r"(a[2]), "r"(a[3]), "r"(b[0]), "r"(b[1]));
}

#define CP_ASYNC16(smem, gptr) \
    asm volatile("cp.async.cg.shared.global [%0], [%1], 16;" \
                 :: "r"(smem), "l"(gptr))
#define CP_COMMIT() asm volatile("cp.async.commit_group;" ::: "memory")
#define CP_WAIT1()  asm volatile("cp.async.wait_group 1;" ::: "memory")

// sincos accurate under --use_fast_math (Cody-Waite 2*pi reduction)
__device__ __forceinline__ void sincos_red(float ang, float* s, float* c) {
    float kf = rintf(ang * 0.15915494309189535f);
    float r = fmaf(kf, -6.2831854820251465f, ang);
    r = fmaf(kf, 1.7484555e-7f, r);
    __sincosf(r, s, c);
}

__device__ __forceinline__ uint32_t pack_h2(float p0, float p1) {
    __half2 hp; hp.x = __float2half_rn(p0); hp.y = __float2half_rn(p1);
    return *(uint32_t*)&hp;
}

// ---------------------------------------------------------------------------
// One-launch fp32 -> fp16 conversion of x (4M elems, y=0..3) and the four
// weight matrices (1M each, y=4..7).
// ---------------------------------------------------------------------------
__global__ __launch_bounds__(256)
void convert_all_kernel(const float* __restrict__ x,
                        const float* __restrict__ w0, const float* __restrict__ w1,
                        const float* __restrict__ w2, const float* __restrict__ w3,
                        __half* __restrict__ xo,
                        __half* __restrict__ f0, __half* __restrict__ f1,
                        __half* __restrict__ f2, __half* __restrict__ f3)
{
    int y = blockIdx.y;
    const float* src;
    __half* dst;
    if (y < 4)       { src = x  + (size_t)y * 1048576; dst = xo + (size_t)y * 1048576; }
    else if (y == 4) { src = w0; dst = f0; }
    else if (y == 5) { src = w1; dst = f1; }
    else if (y == 6) { src = w2; dst = f2; }
    else             { src = w3; dst = f3; }
    int i = (blockIdx.x * 256 + threadIdx.x) * 4;
    float4 v = *(const float4*)(src + i);
    *(uint32_t*)&dst[i]     = pack_h2(v.x, v.y);
    *(uint32_t*)&dst[i + 2] = pack_h2(v.z, v.w);
}

// ---------------------------------------------------------------------------
// fp16 single-term GEMM core: C[m,n] = sum_k A[m,k]*W[n,k] + bias[n].
// CTA 128x128, 8 warps (2x4), warp 64x32, BK=32, 2-stage cp.async, 2 CTAs/SM.
// ---------------------------------------------------------------------------
#define GBK 32
#define GNCHUNK (Ev / GBK)               // 32
#define GT 10240                         // one 128-row tile (80B pitch)
#define GSTAGE (2 * GT)                  // 20480 (A, W)
#define GEMM_SMEM (2 * GSTAGE + 256)     // 41216

__device__ __forceinline__
void gemm_core(const __half* __restrict__ A,
               const __half* __restrict__ W,
               const float* __restrict__ bias,
               float* __restrict__ dstf,
               __half* __restrict__ dsth, int mode)
{
    extern __shared__ char dsm[];
    uint32_t base = (smem_to_u32(dsm) + 127) & ~127u;

    const int tid = threadIdx.x;
    const int wid = tid >> 5, lid = tid & 31;
    const int wm = wid >> 2, wn = wid & 3;       // 2x4 warp grid
    const int m0 = blockIdx.y * 128, n0 = blockIdx.x * 128;

    const __half* srcs[2] = { A + (size_t)m0 * Ev, W + (size_t)n0 * Ev };

    auto load_chunk = [&](int c, int s) {
        const int k0 = c * GBK;
        uint32_t sb = base + s * GSTAGE;
        #pragma unroll
        for (int it = 0; it < 4; it++) {
            int e = it * 256 + tid;
            int c16 = e & 3;
            int grow = e >> 2;                  // 0..255
            int tile = grow >> 7, row = grow & 127;
            uint32_t so = sb + tile * GT + row * 80 + c16 * 16;
            const void* g = srcs[tile] + (size_t)row * Ev + k0 + c16 * 8;
            CP_ASYNC16(so, g);
        }
    };

    float acc[4][4][4] = {};

    const uint32_t aoff = (lid & 15) * 80 + (lid >> 4) * 16;
    const uint32_t boff = ((lid >> 4) * 8 + (lid & 7)) * 80 + ((lid >> 3) & 1) * 16;

    load_chunk(0, 0);
    CP_COMMIT();

    for (int c = 0; c < GNCHUNK; c++) {
        if (c + 1 < GNCHUNK) load_chunk(c + 1, (c + 1) & 1);
        CP_COMMIT();
        CP_WAIT1();
        __syncthreads();

        uint32_t sb = base + (c & 1) * GSTAGE;
        uint32_t aT = sb + (wm * 64) * 80;
        uint32_t bW = sb + GT + (wn * 32) * 80;

        #pragma unroll
        for (int ks = 0; ks < 2; ks++) {
            uint32_t kb = ks * 32;
            uint32_t bh[4][2];
            #pragma unroll
            for (int pr = 0; pr < 2; pr++) {
                uint32_t t4[4];
                ldmatrix_x4(t4, bW + pr * (16 * 80) + kb + boff);
                bh[2 * pr][0] = t4[0]; bh[2 * pr][1] = t4[1];
                bh[2 * pr + 1][0] = t4[2]; bh[2 * pr + 1][1] = t4[3];
            }
            uint32_t ah[4][4];
            #pragma unroll
            for (int mt = 0; mt < 4; mt++)
                ldmatrix_x4(ah[mt], aT + mt * (16 * 80) + kb + aoff);
            #pragma unroll
            for (int mt = 0; mt < 4; mt++)
                #pragma unroll
                for (int nt = 0; nt < 4; nt++)
                    mma16816h(acc[mt][nt], ah[mt], bh[nt]);
        }
        __syncthreads();
    }

    // ------------------- epilogue -------------------
    const int g4 = lid >> 2, t2 = lid & 3;
    #pragma unroll
    for (int nt = 0; nt < 4; nt++) {
        int n = n0 + wn * 32 + nt * 8 + t2 * 2;
        float bi0 = bias[n], bi1 = bias[n + 1];
        int h = n >> 6, d = n & 63;
        float fe = 0.f, fo = 0.f;
        if (mode == MODE_ROPEQ || mode == MODE_ROPEK) {
            fe = powf(10000.0f, -(float)(2 * (d & 31)) / 64.0f);
            fo = powf(10000.0f, -(float)(2 * ((d + 1) & 31)) / 64.0f);
        }
        #pragma unroll
        for (int mt = 0; mt < 4; mt++) {
            #pragma unroll
            for (int hf = 0; hf < 2; hf++) {
                int m = m0 + wm * 64 + mt * 16 + g4 + hf * 8;
                float v0 = acc[mt][nt][hf * 2 + 0] + bi0;
                float v1 = acc[mt][nt][hf * 2 + 1] + bi1;
                if (mode == MODE_PLAIN) {
                    float2 o = {v0, v1};
                    *(float2*)&dstf[(size_t)m * Ev + n] = o;
                } else {
                    int b = m >> 11, srow = m & 2047;
                    if (mode != MODE_BHSD) {
                        float pos = (float)srow;
                        float se, ce, so, co;
                        sincos_red(pos * fe, &se, &ce);
                        sincos_red(pos * fo, &so, &co);
                        float r0 = v0 * ce - v1 * se;
                        float r1 = v1 * co + v0 * so;
                        v0 = r0; v1 = r1;
                        // Q: fold 1/sqrt(64) AND 1/ln2 (softmax uses exp2)
                        if (mode == MODE_ROPEQ) {
                            v0 *= 0.18033688011112042f;
                            v1 *= 0.18033688011112042f;
                        }
                    }
                    size_t off = (((size_t)(b * Hv + h) * Sv + srow) << 6) + d;
                    *(uint32_t*)&dsth[off] = pack_h2(v0, v1);
                }
            }
        }
    }
}

__global__ __launch_bounds__(256, 2)
void gemm_qkv_kernel(const __half* __restrict__ x,
                     const __half* __restrict__ wq, const __half* __restrict__ wk,
                     const __half* __restrict__ wv,
                     const float* __restrict__ bq, const float* __restrict__ bk,
                     const float* __restrict__ bv,
                     __half* __restrict__ qq, __half* __restrict__ kk,
                     __half* __restrict__ vv)
{
    int z = blockIdx.z;
    const __half* w = (z == 0) ? wq : (z == 1) ? wk : wv;
    const float* bias = (z == 0) ? bq : (z == 1) ? bk : bv;
    __half* dst = (z == 0) ? qq : (z == 1) ? kk : vv;
    int mode = (z == 0) ? MODE_ROPEQ : (z == 1) ? MODE_ROPEK : MODE_BHSD;
    gemm_core(x, w, bias, nullptr, dst, mode);
}

__global__ __launch_bounds__(256, 2)
void gemm_final_kernel(const __half* __restrict__ oo,
                       const __half* __restrict__ wo,
                       const float* __restrict__ bo, float* __restrict__ out)
{
    gemm_core(oo, wo, bo, out, nullptr, MODE_PLAIN);
}

// ---------------------------------------------------------------------------
// Flash attention, pure fp16 operands (fp32 accum): S = q*K, O = p*V.
// Software-pipelined S, base-2 softmax. CTA = 64 queries (4 warps),
// 3 KV stages, 2 CTAs/SM.
// ---------------------------------------------------------------------------
#define PITCHB 144
#define NQ 64
#define QSMB (NQ * PITCHB)           // 9216
#define KVTILE (64 * PITCHB)         // 9216
#define KVSTG (2 * KVTILE)           // 18432 (K + V)
#define ATTN_SMEM (3 * KVSTG)        // 55296

__global__ __launch_bounds__(128, 2)
void attn_mma_kernel(const __half* __restrict__ Qq,
                     const __half* __restrict__ Kk, const __half* __restrict__ Vv,
                     __half* __restrict__ Oo)
{
    extern __shared__ char dsm[];
    uint32_t stg = smem_to_u32(dsm);
    const int tid = threadIdx.x, wid = tid >> 5, lid = tid & 31;
    const int qt = (int)gridDim.x - 1 - (int)blockIdx.x;  // longest first
    const int bh = blockIdx.y;
    const int nkt = qt + 1;
    const size_t bhb = (size_t)bh * Sv * 64;

    auto stage_addr = [&](int s) { return stg + (uint32_t)s * KVSTG; };

    auto load_kv = [&](int kt, int s) {
        uint32_t sb = stage_addr(s);
        const __half* srcs[2] = {
            Kk + bhb + (size_t)kt * 64 * 64, Vv + bhb + (size_t)kt * 64 * 64 };
        #pragma unroll
        for (int it = 0; it < 8; it++) {
            int e = it * 128 + tid;
            int tl = e >> 9, r = (e >> 3) & 63, ch = e & 7;
            CP_ASYNC16(sb + tl * KVTILE + r * PITCHB + ch * 16,
                       srcs[tl] + r * 64 + ch * 8);
        }
    };

    // ---- prologue: Q -> stage2 region (temp), KV(0), KV(1) ----
    const uint32_t qtmp = stage_addr(2);
    {
        const __half* gq = Qq + bhb + (size_t)qt * NQ * 64;
        #pragma unroll
        for (int it = 0; it < 4; it++) {
            int e = it * 128 + tid;
            int r = e >> 3, ch = e & 7;
            CP_ASYNC16(qtmp + r * PITCHB + ch * 16, gq + r * 64 + ch * 8);
        }
        load_kv(0, 0);
        CP_COMMIT();                 // G0 = Q + KV(0)
        if (nkt > 1) load_kv(1, 1);
        CP_COMMIT();                 // G1 = KV(1)
    }
    CP_WAIT1();                      // G0 done
    __syncthreads();

    // Q fragments (register resident)
    uint32_t qf[4][4];
    {
        uint32_t qfo = (wid * 16 + (lid & 15)) * PITCHB + (lid >> 4) * 16;
        #pragma unroll
        for (int kc = 0; kc < 4; kc++)
            ldmatrix_x4(qf[kc], qtmp + qfo + kc * 32);
    }

    const uint32_t kfo = ((lid >> 4) * 8 + (lid & 7)) * PITCHB + ((lid >> 3) & 1) * 16;
    const uint32_t vfo = (lid & 15) * PITCHB + (lid >> 4) * 16;
    const int g4 = lid >> 2, t2 = lid & 3;

    // Single-term S with interleaved accumulators (RAW spacing 4).
    auto compute_S = [&](float (&Sd)[8][4], int stage) {
        #pragma unroll
        for (int nt = 0; nt < 8; nt++)
            #pragma unroll
            for (int i = 0; i < 4; i++) Sd[nt][i] = 0.f;
        uint32_t sb = stage_addr(stage);
        #pragma unroll
        for (int kc = 0; kc < 4; kc++) {
            #pragma unroll
            for (int pr = 0; pr < 2; pr++) {
                uint32_t kh[2][4];
                #pragma unroll
                for (int j = 0; j < 2; j++) {
                    int n0t = pr * 2 + j;
                    uint32_t ka = sb + (n0t * 16) * PITCHB + kc * 32 + kfo;
                    ldmatrix_x4(kh[j], ka);
                }
                #pragma unroll
                for (int j = 0; j < 2; j++) {
                    int nt = (pr * 2 + j) * 2;
                    mma16816h(Sd[nt], qf[kc], kh[j]);
                    mma16816h(Sd[nt + 1], qf[kc], kh[j] + 2);
                }
            }
        }
    };

    float SA[8][4], SB[8][4];
    compute_S(SA, 0);                // S(0) while stage1/2 loads fly

    __syncthreads();                 // Q region free -> reuse as stage2
    if (nkt > 2) load_kv(2, 2);
    CP_COMMIT();                     // G2
    CP_WAIT1();                      // G1 done (stage1 ready)
    __syncthreads();

    float m0 = -1e30f, m1 = -1e30f, l0 = 0.f, l1 = 0.f;
    float accO[8][4] = {};

    auto body = [&](float (&Scur)[8][4], float (&Snext)[8][4], int kt) {
        // ---- prefetch S for kt+1 (tensor busy during softmax below) ----
        if (kt + 1 < nkt) compute_S(Snext, (kt + 1) % 3);

        // ---- causal mask (diagonal tile only) ----
        if (kt == qt) {
            int j0g = kt * 64, q0g = qt * NQ + wid * 16;
            int colb = t2 * 2, rowb = g4;
            #pragma unroll
            for (int nt = 0; nt < 8; nt++) {
                int jb = j0g + nt * 8 + colb;
                if (jb > q0g + rowb)          Scur[nt][0] = -1e30f;
                if (jb + 1 > q0g + rowb)      Scur[nt][1] = -1e30f;
                if (jb > q0g + rowb + 8)      Scur[nt][2] = -1e30f;
                if (jb + 1 > q0g + rowb + 8)  Scur[nt][3] = -1e30f;
            }
        }

        // ---- online softmax (base-2: scores pre-scaled by 1/ln2) ----
        float mx0 = -1e30f, mx1 = -1e30f;
        #pragma unroll
        for (int nt = 0; nt < 8; nt++) {
            mx0 = fmaxf(mx0, fmaxf(Scur[nt][0], Scur[nt][1]));
            mx1 = fmaxf(mx1, fmaxf(Scur[nt][2], Scur[nt][3]));
        }
        mx0 = fmaxf(mx0, __shfl_xor_sync(0xffffffffu, mx0, 1));
        mx0 = fmaxf(mx0, __shfl_xor_sync(0xffffffffu, mx0, 2));
        mx1 = fmaxf(mx1, __shfl_xor_sync(0xffffffffu, mx1, 1));
        mx1 = fmaxf(mx1, __shfl_xor_sync(0xffffffffu, mx1, 2));
        float nm0 = fmaxf(m0, mx0), nm1 = fmaxf(m1, mx1);
        float a0 = exp2f(m0 - nm0), a1 = exp2f(m1 - nm1);
        m0 = nm0; m1 = nm1;

        float rs0 = 0.f, rs1 = 0.f;
        uint32_t phA[8], phB[8];
        #pragma unroll
        for (int nt = 0; nt < 8; nt++) {
            float p0 = exp2f(Scur[nt][0] - nm0), p1 = exp2f(Scur[nt][1] - nm0);
            float p2 = exp2f(Scur[nt][2] - nm1), p3 = exp2f(Scur[nt][3] - nm1);
            rs0 += p0 + p1; rs1 += p2 + p3;
            phA[nt] = pack_h2(p0, p1);
            phB[nt] = pack_h2(p2, p3);
        }
        rs0 += __shfl_xor_sync(0xffffffffu, rs0, 1);
        rs0 += __shfl_xor_sync(0xffffffffu, rs0, 2);
        rs1 += __shfl_xor_sync(0xffffffffu, rs1, 1);
        rs1 += __shfl_xor_sync(0xffffffffu, rs1, 2);
        l0 = l0 * a0 + rs0;
        l1 = l1 * a1 + rs1;
        #pragma unroll
        for (int dt = 0; dt < 8; dt++) {
            accO[dt][0] *= a0; accO[dt][1] *= a0;
            accO[dt][2] *= a1; accO[dt][3] *= a1;
        }

        // ---- O += p * V, alternate-acc ordering ----
        uint32_t vb = stage_addr(kt % 3) + KVTILE;
        #pragma unroll
        for (int kc = 0; kc < 4; kc++) {
            uint32_t aph[4] = {phA[2 * kc], phB[2 * kc], phA[2 * kc + 1], phB[2 * kc + 1]};
            #pragma unroll
            for (int d0t = 0; d0t < 4; d0t++) {
                uint32_t va = vb + (kc * 16) * PITCHB + d0t * 32 + vfo;
                uint32_t vh[4];
                ldmatrix_x4t(vh, va);
                mma16816h(accO[2 * d0t],     aph, vh);
                mma16816h(accO[2 * d0t + 1], aph, vh + 2);
            }
        }

        // ---- pipeline wind: free stage kt%3, fetch kt+3 into it ----
        __syncthreads();
        if (kt + 3 < nkt) load_kv(kt + 3, kt % 3);
        CP_COMMIT();
        CP_WAIT1();                  // completes load(kt+2), needed next iter
        __syncthreads();
    };

    for (int kt = 0; kt < nkt; kt += 2) {
        body(SA, SB, kt);
        if (kt + 1 < nkt) body(SB, SA, kt + 1);
    }

    // ---- epilogue: normalize, single fp16, write [M, E] ----
    float inv0 = 1.0f / l0, inv1 = 1.0f / l1;
    int b = bh >> 4, h = bh & 15;
    int s0 = qt * NQ + wid * 16 + g4, s1 = s0 + 8;
    size_t r0o = ((size_t)(b * Sv + s0)) * Ev + h * 64;
    size_t r1o = ((size_t)(b * Sv + s1)) * Ev + h * 64;
    #pragma unroll
    for (int dt = 0; dt < 8; dt++) {
        int d = dt * 8 + t2 * 2;
        *(uint32_t*)&Oo[r0o + d] = pack_h2(accO[dt][0] * inv0, accO[dt][1] * inv0);
        *(uint32_t*)&Oo[r1o + d] = pack_h2(accO[dt][2] * inv1, accO[dt][3] * inv1);
    }
}

// ---------------------------------------------------------------------------
extern "C" void kernel_launch(void* const* d_in, const int* in_sizes, int n_in,
                              void* d_out, int out_size)
{
    const float* x  = (const float*)d_in[0];
    const float* wq = (const float*)d_in[1];
    const float* bq = (const float*)d_in[2];
    const float* wk = (const float*)d_in[3];
    const float* bk = (const float*)d_in[4];
    const float* wv = (const float*)d_in[5];
    const float* bv = (const float*)d_in[6];
    const float* wo = (const float*)d_in[7];
    const float* bo = (const float*)d_in[8];
    float* out = (float*)d_out;

    cudaFuncSetAttribute(gemm_qkv_kernel,
                         cudaFuncAttributeMaxDynamicSharedMemorySize, GEMM_SMEM);
    cudaFuncSetAttribute(gemm_final_kernel,
                         cudaFuncAttributeMaxDynamicSharedMemorySize, GEMM_SMEM);
    cudaFuncSetAttribute(attn_mma_kernel,
                         cudaFuncAttributeMaxDynamicSharedMemorySize, ATTN_SMEM);

    __half *qq, *kk, *vv, *xh, *oo, *wqh, *wkh, *wvh, *woh;
    cudaGetSymbolAddress((void**)&qq, g_Q);
    cudaGetSymbolAddress((void**)&kk, g_K);
    cudaGetSymbolAddress((void**)&vv, g_V);
    cudaGetSymbolAddress((void**)&xh, g_x);
    cudaGetSymbolAddress((void**)&oo, g_O);
    cudaGetSymbolAddress((void**)&wqh, g_wq);
    cudaGetSymbolAddress((void**)&wkh, g_wk);
    cudaGetSymbolAddress((void**)&wvh, g_wv);
    cudaGetSymbolAddress((void**)&woh, g_wo);

    // one launch: convert x (4 chunks) + 4 weight matrices to fp16
    convert_all_kernel<<<dim3(1024, 8), 256>>>(
        x, wq, wk, wv, wo, xh, wqh, wkh, wvh, woh);

    gemm_qkv_kernel<<<dim3(Ev / 128, Mtot / 128, 3), 256, GEMM_SMEM>>>(
        xh, wqh, wkh, wvh, bq, bk, bv, qq, kk, vv);

    attn_mma_kernel<<<dim3(Sv / NQ, Bv * Hv), 128, ATTN_SMEM>>>(
        qq, kk, vv, oo);

    gemm_final_kernel<<<dim3(Ev / 128, Mtot / 128), 256, GEMM_SMEM>>>(
        oo, woh, bo, out);
}

// round 17
// speedup vs baseline: 2.5246x; 1.0512x over previous
#include <cuda_runtime.h>
#include <cuda_bf16.h>
#include <cuda_fp16.h>
#include <cstdint>
#include <math.h>

#define Bv 2
#define Sv 2048
#define Ev 1024
#define Hv 16
#define Dv 64
#define Mtot (Bv * Sv)          // 4096

enum { MODE_ROPEQ = 0, MODE_ROPEK = 1, MODE_BHSD = 2, MODE_PLAIN = 3 };

// ---------------- scratch (__device__ globals; no allocs allowed) ----------
__device__ __half g_Q[Bv * Hv * Sv * Dv];
__device__ __half g_K[Bv * Hv * Sv * Dv];
__device__ __half g_V[Bv * Hv * Sv * Dv];
__device__ __half g_x[Mtot * Ev];
__device__ __half g_O[Mtot * Ev];
__device__ __half g_wq[Ev * Ev], g_wk[Ev * Ev], g_wv[Ev * Ev], g_wo[Ev * Ev];

// ---------------- helpers --------------------------------------------------
__device__ __forceinline__ uint32_t smem_to_u32(const void* p) {
    uint32_t a;
    asm("{ .reg .u64 t; cvta.to.shared.u64 t, %1; cvt.u32.u64 %0, t; }"
        : "=r"(a) : "l"(p));
    return a;
}

__device__ __forceinline__ void ldmatrix_x4(uint32_t* r, uint32_t addr) {
    asm volatile("ldmatrix.sync.aligned.m8n8.x4.shared.b16 {%0,%1,%2,%3}, [%4];"
                 : "=r"(r[0]), "=r"(r[1]), "=r"(r[2]), "=r"(r[3]) : "r"(addr));
}
__device__ __forceinline__ void ldmatrix_x4t(uint32_t* r, uint32_t addr) {
    asm volatile("ldmatrix.sync.aligned.m8n8.x4.trans.shared.b16 {%0,%1,%2,%3}, [%4];"
                 : "=r"(r[0]), "=r"(r[1]), "=r"(r[2]), "=r"(r[3]) : "r"(addr));
}

// fp16 inputs, fp32 accumulate
__device__ __forceinline__ void mma16816h(float* c, const uint32_t* a,
                                          const uint32_t* b) {
    asm volatile(
        "mma.sync.aligned.m16n8k16.row.col.f32.f16.f16.f32 "
        "{%0,%1,%2,%3}, {%4,%5,%6,%7}, {%8,%9}, {%0,%1,%2,%3};"
        : "+f"(c[0]), "+f"(c[1]), "+f"(c[2]), "+f"(c[3])
        : "r"(a[0]), "r"(a[1]), "r"(a[2]), "r"(a[3]), "r"(b[0]), "r"(b[1]));
}

#define CP_ASYNC16(smem, gptr) \
    asm volatile("cp.async.cg.shared.global [%0], [%1], 16;" \
                 :: "r"(smem), "l"(gptr))
#define CP_COMMIT() asm volatile("cp.async.commit_group;" ::: "memory")
#define CP_WAIT1()  asm volatile("cp.async.wait_group 1;" ::: "memory")

// sincos accurate under --use_fast_math (Cody-Waite 2*pi reduction)
__device__ __forceinline__ void sincos_red(float ang, float* s, float* c) {
    float kf = rintf(ang * 0.15915494309189535f);
    float r = fmaf(kf, -6.2831854820251465f, ang);
    r = fmaf(kf, 1.7484555e-7f, r);
    __sincosf(r, s, c);
}

__device__ __forceinline__ uint32_t pack_h2(float p0, float p1) {
    __half2 hp; hp.x = __float2half_rn(p0); hp.y = __float2half_rn(p1);
    return *(uint32_t*)&hp;
}

// ---------------------------------------------------------------------------
// One-launch fp32 -> fp16 conversion of x (4M elems, y=0..3) and the four
// weight matrices (1M each, y=4..7).
// ---------------------------------------------------------------------------
__global__ __launch_bounds__(256)
void convert_all_kernel(const float* __restrict__ x,
                        const float* __restrict__ w0, const float* __restrict__ w1,
                        const float* __restrict__ w2, const float* __restrict__ w3,
                        __half* __restrict__ xo,
                        __half* __restrict__ f0, __half* __restrict__ f1,
                        __half* __restrict__ f2, __half* __restrict__ f3)
{
    int y = blockIdx.y;
    const float* src;
    __half* dst;
    if (y < 4)       { src = x  + (size_t)y * 1048576; dst = xo + (size_t)y * 1048576; }
    else if (y == 4) { src = w0; dst = f0; }
    else if (y == 5) { src = w1; dst = f1; }
    else if (y == 6) { src = w2; dst = f2; }
    else             { src = w3; dst = f3; }
    int i = (blockIdx.x * 256 + threadIdx.x) * 4;
    float4 v = *(const float4*)(src + i);
    *(uint32_t*)&dst[i]     = pack_h2(v.x, v.y);
    *(uint32_t*)&dst[i + 2] = pack_h2(v.z, v.w);
}

// ---------------------------------------------------------------------------
// fp16 single-term GEMM core: C[m,n] = sum_k A[m,k]*W[n,k] + bias[n].
// CTA 128x128, 8 warps (2x4), warp 64x32, BK=64 (4 k-steps per barrier),
// 2-stage cp.async, 2 CTAs/SM. Rows padded to 144B (9x16B, conflict-free).
// ---------------------------------------------------------------------------
#define GBK 64
#define GNCHUNK (Ev / GBK)               // 16
#define GPITCH 144
#define GT (128 * GPITCH)                // 18432 per tile
#define GSTAGE (2 * GT)                  // 36864 (A, W)
#define GEMM_SMEM (2 * GSTAGE + 256)     // 73984

__device__ __forceinline__
void gemm_core(const __half* __restrict__ A,
               const __half* __restrict__ W,
               const float* __restrict__ bias,
               float* __restrict__ dstf,
               __half* __restrict__ dsth, int mode)
{
    extern __shared__ char dsm[];
    uint32_t base = (smem_to_u32(dsm) + 127) & ~127u;

    const int tid = threadIdx.x;
    const int wid = tid >> 5, lid = tid & 31;
    const int wm = wid >> 2, wn = wid & 3;       // 2x4 warp grid
    const int m0 = blockIdx.y * 128, n0 = blockIdx.x * 128;

    const __half* srcs[2] = { A + (size_t)m0 * Ev, W + (size_t)n0 * Ev };

    auto load_chunk = [&](int c, int s) {
        const int k0 = c * GBK;
        uint32_t sb = base + s * GSTAGE;
        #pragma unroll
        for (int it = 0; it < 8; it++) {
            int e = it * 256 + tid;
            int c16 = e & 7;                    // 8 x 16B per 128B row
            int grow = e >> 3;                  // 0..255
            int tile = grow >> 7, row = grow & 127;
            uint32_t so = sb + tile * GT + row * GPITCH + c16 * 16;
            const void* g = srcs[tile] + (size_t)row * Ev + k0 + c16 * 8;
            CP_ASYNC16(so, g);
        }
    };

    float acc[4][4][4] = {};

    const uint32_t aoff = (lid & 15) * GPITCH + (lid >> 4) * 16;
    const uint32_t boff = ((lid >> 4) * 8 + (lid & 7)) * GPITCH + ((lid >> 3) & 1) * 16;

    load_chunk(0, 0);
    CP_COMMIT();

    for (int c = 0; c < GNCHUNK; c++) {
        if (c + 1 < GNCHUNK) load_chunk(c + 1, (c + 1) & 1);
        CP_COMMIT();
        CP_WAIT1();
        __syncthreads();

        uint32_t sb = base + (c & 1) * GSTAGE;
        uint32_t aT = sb + (wm * 64) * GPITCH;
        uint32_t bW = sb + GT + (wn * 32) * GPITCH;

        #pragma unroll
        for (int ks = 0; ks < 4; ks++) {
            uint32_t kb = ks * 32;              // 16 halves = 32 bytes
            uint32_t bh[4][2];
            #pragma unroll
            for (int pr = 0; pr < 2; pr++) {
                uint32_t t4[4];
                ldmatrix_x4(t4, bW + pr * (16 * GPITCH) + kb + boff);
                bh[2 * pr][0] = t4[0]; bh[2 * pr][1] = t4[1];
                bh[2 * pr + 1][0] = t4[2]; bh[2 * pr + 1][1] = t4[3];
            }
            uint32_t ah[4][4];
            #pragma unroll
            for (int mt = 0; mt < 4; mt++)
                ldmatrix_x4(ah[mt], aT + mt * (16 * GPITCH) + kb + aoff);
            #pragma unroll
            for (int mt = 0; mt < 4; mt++)
                #pragma unroll
                for (int nt = 0; nt < 4; nt++)
                    mma16816h(acc[mt][nt], ah[mt], bh[nt]);
        }
        __syncthreads();
    }

    // ------------------- epilogue -------------------
    const int g4 = lid >> 2, t2 = lid & 3;
    #pragma unroll
    for (int nt = 0; nt < 4; nt++) {
        int n = n0 + wn * 32 + nt * 8 + t2 * 2;
        float bi0 = bias[n], bi1 = bias[n + 1];
        int h = n >> 6, d = n & 63;
        float fe = 0.f, fo = 0.f;
        if (mode == MODE_ROPEQ || mode == MODE_ROPEK) {
            fe = powf(10000.0f, -(float)(2 * (d & 31)) / 64.0f);
            fo = powf(10000.0f, -(float)(2 * ((d + 1) & 31)) / 64.0f);
        }
        #pragma unroll
        for (int mt = 0; mt < 4; mt++) {
            #pragma unroll
            for (int hf = 0; hf < 2; hf++) {
                int m = m0 + wm * 64 + mt * 16 + g4 + hf * 8;
                float v0 = acc[mt][nt][hf * 2 + 0] + bi0;
                float v1 = acc[mt][nt][hf * 2 + 1] + bi1;
                if (mode == MODE_PLAIN) {
                    float2 o = {v0, v1};
                    *(float2*)&dstf[(size_t)m * Ev + n] = o;
                } else {
                    int b = m >> 11, srow = m & 2047;
                    if (mode != MODE_BHSD) {
                        float pos = (float)srow;
                        float se, ce, so, co;
                        sincos_red(pos * fe, &se, &ce);
                        sincos_red(pos * fo, &so, &co);
                        float r0 = v0 * ce - v1 * se;
                        float r1 = v1 * co + v0 * so;
                        v0 = r0; v1 = r1;
                        // Q: fold 1/sqrt(64) AND 1/ln2 (softmax uses exp2)
                        if (mode == MODE_ROPEQ) {
                            v0 *= 0.18033688011112042f;
                            v1 *= 0.18033688011112042f;
                        }
                    }
                    size_t off = (((size_t)(b * Hv + h) * Sv + srow) << 6) + d;
                    *(uint32_t*)&dsth[off] = pack_h2(v0, v1);
                }
            }
        }
    }
}

__global__ __launch_bounds__(256, 2)
void gemm_qkv_kernel(const __half* __restrict__ x,
                     const __half* __restrict__ wq, const __half* __restrict__ wk,
                     const __half* __restrict__ wv,
                     const float* __restrict__ bq, const float* __restrict__ bk,
                     const float* __restrict__ bv,
                     __half* __restrict__ qq, __half* __restrict__ kk,
                     __half* __restrict__ vv)
{
    int z = blockIdx.z;
    const __half* w = (z == 0) ? wq : (z == 1) ? wk : wv;
    const float* bias = (z == 0) ? bq : (z == 1) ? bk : bv;
    __half* dst = (z == 0) ? qq : (z == 1) ? kk : vv;
    int mode = (z == 0) ? MODE_ROPEQ : (z == 1) ? MODE_ROPEK : MODE_BHSD;
    gemm_core(x, w, bias, nullptr, dst, mode);
}

__global__ __launch_bounds__(256, 2)
void gemm_final_kernel(const __half* __restrict__ oo,
                       const __half* __restrict__ wo,
                       const float* __restrict__ bo, float* __restrict__ out)
{
    gemm_core(oo, wo, bo, out, nullptr, MODE_PLAIN);
}

// ---------------------------------------------------------------------------
// Flash attention, pure fp16 operands (fp32 accum): S = q*K, O = p*V.
// Software-pipelined S, base-2 softmax. CTA = 64 queries (4 warps),
// 3 KV stages, 2 CTAs/SM.
// ---------------------------------------------------------------------------
#define PITCHB 144
#define NQ 64
#define QSMB (NQ * PITCHB)           // 9216
#define KVTILE (64 * PITCHB)         // 9216
#define KVSTG (2 * KVTILE)           // 18432 (K + V)
#define ATTN_SMEM (3 * KVSTG)        // 55296

__global__ __launch_bounds__(128, 2)
void attn_mma_kernel(const __half* __restrict__ Qq,
                     const __half* __restrict__ Kk, const __half* __restrict__ Vv,
                     __half* __restrict__ Oo)
{
    extern __shared__ char dsm[];
    uint32_t stg = smem_to_u32(dsm);
    const int tid = threadIdx.x, wid = tid >> 5, lid = tid & 31;
    const int qt = (int)gridDim.x - 1 - (int)blockIdx.x;  // longest first
    const int bh = blockIdx.y;
    const int nkt = qt + 1;
    const size_t bhb = (size_t)bh * Sv * 64;

    auto stage_addr = [&](int s) { return stg + (uint32_t)s * KVSTG; };

    auto load_kv = [&](int kt, int s) {
        uint32_t sb = stage_addr(s);
        const __half* srcs[2] = {
            Kk + bhb + (size_t)kt * 64 * 64, Vv + bhb + (size_t)kt * 64 * 64 };
        #pragma unroll
        for (int it = 0; it < 8; it++) {
            int e = it * 128 + tid;
            int tl = e >> 9, r = (e >> 3) & 63, ch = e & 7;
            CP_ASYNC16(sb + tl * KVTILE + r * PITCHB + ch * 16,
                       srcs[tl] + r * 64 + ch * 8);
        }
    };

    // ---- prologue: Q -> stage2 region (temp), KV(0), KV(1) ----
    const uint32_t qtmp = stage_addr(2);
    {
        const __half* gq = Qq + bhb + (size_t)qt * NQ * 64;
        #pragma unroll
        for (int it = 0; it < 4; it++) {
            int e = it * 128 + tid;
            int r = e >> 3, ch = e & 7;
            CP_ASYNC16(qtmp + r * PITCHB + ch * 16, gq + r * 64 + ch * 8);
        }
        load_kv(0, 0);
        CP_COMMIT();                 // G0 = Q + KV(0)
        if (nkt > 1) load_kv(1, 1);
        CP_COMMIT();                 // G1 = KV(1)
    }
    CP_WAIT1();                      // G0 done
    __syncthreads();

    // Q fragments (register resident)
    uint32_t qf[4][4];
    {
        uint32_t qfo = (wid * 16 + (lid & 15)) * PITCHB + (lid >> 4) * 16;
        #pragma unroll
        for (int kc = 0; kc < 4; kc++)
            ldmatrix_x4(qf[kc], qtmp + qfo + kc * 32);
    }

    const uint32_t kfo = ((lid >> 4) * 8 + (lid & 7)) * PITCHB + ((lid >> 3) & 1) * 16;
    const uint32_t vfo = (lid & 15) * PITCHB + (lid >> 4) * 16;
    const int g4 = lid >> 2, t2 = lid & 3;

    // Single-term S with interleaved accumulators (RAW spacing 4).
    auto compute_S = [&](float (&Sd)[8][4], int stage) {
        #pragma unroll
        for (int nt = 0; nt < 8; nt++)
            #pragma unroll
            for (int i = 0; i < 4; i++) Sd[nt][i] = 0.f;
        uint32_t sb = stage_addr(stage);
        #pragma unroll
        for (int kc = 0; kc < 4; kc++) {
            #pragma unroll
            for (int pr = 0; pr < 2; pr++) {
                uint32_t kh[2][4];
                #pragma unroll
                for (int j = 0; j < 2; j++) {
                    int n0t = pr * 2 + j;
                    uint32_t ka = sb + (n0t * 16) * PITCHB + kc * 32 + kfo;
                    ldmatrix_x4(kh[j], ka);
                }
                #pragma unroll
                for (int j = 0; j < 2; j++) {
                    int nt = (pr * 2 + j) * 2;
                    mma16816h(Sd[nt], qf[kc], kh[j]);
                    mma16816h(Sd[nt + 1], qf[kc], kh[j] + 2);
                }
            }
        }
    };

    float SA[8][4], SB[8][4];
    compute_S(SA, 0);                // S(0) while stage1/2 loads fly

    __syncthreads();                 // Q region free -> reuse as stage2
    if (nkt > 2) load_kv(2, 2);
    CP_COMMIT();                     // G2
    CP_WAIT1();                      // G1 done (stage1 ready)
    __syncthreads();

    float m0 = -1e30f, m1 = -1e30f, l0 = 0.f, l1 = 0.f;
    float accO[8][4] = {};

    auto body = [&](float (&Scur)[8][4], float (&Snext)[8][4], int kt) {
        // ---- prefetch S for kt+1 (tensor busy during softmax below) ----
        if (kt + 1 < nkt) compute_S(Snext, (kt + 1) % 3);

        // ---- causal mask (diagonal tile only) ----
        if (kt == qt) {
            int j0g = kt * 64, q0g = qt * NQ + wid * 16;
            int colb = t2 * 2, rowb = g4;
            #pragma unroll
            for (int nt = 0; nt < 8; nt++) {
                int jb = j0g + nt * 8 + colb;
                if (jb > q0g + rowb)          Scur[nt][0] = -1e30f;
                if (jb + 1 > q0g + rowb)      Scur[nt][1] = -1e30f;
                if (jb > q0g + rowb + 8)      Scur[nt][2] = -1e30f;
                if (jb + 1 > q0g + rowb + 8)  Scur[nt][3] = -1e30f;
            }
        }

        // ---- online softmax (base-2: scores pre-scaled by 1/ln2) ----
        float mx0 = -1e30f, mx1 = -1e30f;
        #pragma unroll
        for (int nt = 0; nt < 8; nt++) {
            mx0 = fmaxf(mx0, fmaxf(Scur[nt][0], Scur[nt][1]));
            mx1 = fmaxf(mx1, fmaxf(Scur[nt][2], Scur[nt][3]));
        }
        mx0 = fmaxf(mx0, __shfl_xor_sync(0xffffffffu, mx0, 1));
        mx0 = fmaxf(mx0, __shfl_xor_sync(0xffffffffu, mx0, 2));
        mx1 = fmaxf(mx1, __shfl_xor_sync(0xffffffffu, mx1, 1));
        mx1 = fmaxf(mx1, __shfl_xor_sync(0xffffffffu, mx1, 2));
        float nm0 = fmaxf(m0, mx0), nm1 = fmaxf(m1, mx1);
        float a0 = exp2f(m0 - nm0), a1 = exp2f(m1 - nm1);
        m0 = nm0; m1 = nm1;

        float rs0 = 0.f, rs1 = 0.f;
        uint32_t phA[8], phB[8];
        #pragma unroll
        for (int nt = 0; nt < 8; nt++) {
            float p0 = exp2f(Scur[nt][0] - nm0), p1 = exp2f(Scur[nt][1] - nm0);
            float p2 = exp2f(Scur[nt][2] - nm1), p3 = exp2f(Scur[nt][3] - nm1);
            rs0 += p0 + p1; rs1 += p2 + p3;
            phA[nt] = pack_h2(p0, p1);
            phB[nt] = pack_h2(p2, p3);
        }
        rs0 += __shfl_xor_sync(0xffffffffu, rs0, 1);
        rs0 += __shfl_xor_sync(0xffffffffu, rs0, 2);
        rs1 += __shfl_xor_sync(0xffffffffu, rs1, 1);
        rs1 += __shfl_xor_sync(0xffffffffu, rs1, 2);
        l0 = l0 * a0 + rs0;
        l1 = l1 * a1 + rs1;
        #pragma unroll
        for (int dt = 0; dt < 8; dt++) {
            accO[dt][0] *= a0; accO[dt][1] *= a0;
            accO[dt][2] *= a1; accO[dt][3] *= a1;
        }

        // ---- O += p * V, alternate-acc ordering ----
        uint32_t vb = stage_addr(kt % 3) + KVTILE;
        #pragma unroll
        for (int kc = 0; kc < 4; kc++) {
            uint32_t aph[4] = {phA[2 * kc], phB[2 * kc], phA[2 * kc + 1], phB[2 * kc + 1]};
            #pragma unroll
            for (int d0t = 0; d0t < 4; d0t++) {
                uint32_t va = vb + (kc * 16) * PITCHB + d0t * 32 + vfo;
                uint32_t vh[4];
                ldmatrix_x4t(vh, va);
                mma16816h(accO[2 * d0t],     aph, vh);
                mma16816h(accO[2 * d0t + 1], aph, vh + 2);
            }
        }

        // ---- pipeline wind: free stage kt%3, fetch kt+3 into it ----
        __syncthreads();
        if (kt + 3 < nkt) load_kv(kt + 3, kt % 3);
        CP_COMMIT();
        CP_WAIT1();                  // completes load(kt+2), needed next iter
        __syncthreads();
    };

    for (int kt = 0; kt < nkt; kt += 2) {
        body(SA, SB, kt);
        if (kt + 1 < nkt) body(SB, SA, kt + 1);
    }

    // ---- epilogue: normalize, single fp16, write [M, E] ----
    float inv0 = 1.0f / l0, inv1 = 1.0f / l1;
    int b = bh >> 4, h = bh & 15;
    int s0 = qt * NQ + wid * 16 + g4, s1 = s0 + 8;
    size_t r0o = ((size_t)(b * Sv + s0)) * Ev + h * 64;
    size_t r1o = ((size_t)(b * Sv + s1)) * Ev + h * 64;
    #pragma unroll
    for (int dt = 0; dt < 8; dt++) {
        int d = dt * 8 + t2 * 2;
        *(uint32_t*)&Oo[r0o + d] = pack_h2(accO[dt][0] * inv0, accO[dt][1] * inv0);
        *(uint32_t*)&Oo[r1o + d] = pack_h2(accO[dt][2] * inv1, accO[dt][3] * inv1);
    }
}

// ---------------------------------------------------------------------------
extern "C" void kernel_launch(void* const* d_in, const int* in_sizes, int n_in,
                              void* d_out, int out_size)
{
    const float* x  = (const float*)d_in[0];
    const float* wq = (const float*)d_in[1];
    const float* bq = (const float*)d_in[2];
    const float* wk = (const float*)d_in[3];
    const float* bk = (const float*)d_in[4];
    const float* wv = (const float*)d_in[5];
    const float* bv = (const float*)d_in[6];
    const float* wo = (const float*)d_in[7];
    const float* bo = (const float*)d_in[8];
    float* out = (float*)d_out;

    cudaFuncSetAttribute(gemm_qkv_kernel,
                         cudaFuncAttributeMaxDynamicSharedMemorySize, GEMM_SMEM);
    cudaFuncSetAttribute(gemm_final_kernel,
                         cudaFuncAttributeMaxDynamicSharedMemorySize, GEMM_SMEM);
    cudaFuncSetAttribute(attn_mma_kernel,
                         cudaFuncAttributeMaxDynamicSharedMemorySize, ATTN_SMEM);

    __half *qq, *kk, *vv, *xh, *oo, *wqh, *wkh, *wvh, *woh;
    cudaGetSymbolAddress((void**)&qq, g_Q);
    cudaGetSymbolAddress((void**)&kk, g_K);
    cudaGetSymbolAddress((void**)&vv, g_V);
    cudaGetSymbolAddress((void**)&xh, g_x);
    cudaGetSymbolAddress((void**)&oo, g_O);
    cudaGetSymbolAddress((void**)&wqh, g_wq);
    cudaGetSymbolAddress((void**)&wkh, g_wk);
    cudaGetSymbolAddress((void**)&wvh, g_wv);
    cudaGetSymbolAddress((void**)&woh, g_wo);

    // one launch: convert x (4 chunks) + 4 weight matrices to fp16
    convert_all_kernel<<<dim3(1024, 8), 256>>>(
        x, wq, wk, wv, wo, xh, wqh, wkh, wvh, woh);

    gemm_qkv_kernel<<<dim3(Ev / 128, Mtot / 128, 3), 256, GEMM_SMEM>>>(
        xh, wqh, wkh, wvh, bq, bk, bv, qq, kk, vv);

    attn_mma_kernel<<<dim3(Sv / NQ, Bv * Hv), 128, ATTN_SMEM>>>(
        qq, kk, vv, oo);

    gemm_final_kernel<<<dim3(Ev / 128, Mtot / 128), 256, GEMM_SMEM>>>(
        oo, woh, bo, out);
}